// round 1
// baseline (speedup 1.0000x reference)
#include <cuda_runtime.h>

#define S_LEN 4096
#define E_DIM 1024
#define H_NUM 16
#define HD    64
#define WSZ   512
#define NTILE 12   // 1536 collected keys / 128

// Scratch (allocation-free rule: __device__ globals). 64 MB total.
__device__ float g_q[H_NUM * S_LEN * HD];
__device__ float g_k[H_NUM * S_LEN * HD];
__device__ float g_v[H_NUM * S_LEN * HD];
__device__ float g_att[S_LEN * E_DIM];

// ---------------------------------------------------------------------------
// GEMM: dst = A[M,K] @ W[N,K]^T + bias[N]   (M=4096, N=K=1024)
// HEADSPLIT=1 -> store to [h][s][d] layout (h=n>>6, d=n&63)
// 128x128 block, BK=16, 256 threads, 8x8 per-thread micro-tile.
// ---------------------------------------------------------------------------
template<int HEADSPLIT>
__global__ __launch_bounds__(256)
void gemm_bias_kernel(const float* __restrict__ A, const float* __restrict__ W,
                      const float* __restrict__ bias, float* __restrict__ dst)
{
    const int K = E_DIM;
    __shared__ float As[16][128];
    __shared__ float Bs[16][128];
    const int tid = threadIdx.x;
    const int tx = tid & 15, ty = tid >> 4;
    const int m0 = blockIdx.y * 128, n0 = blockIdx.x * 128;

    float acc[8][8];
#pragma unroll
    for (int i = 0; i < 8; i++)
#pragma unroll
        for (int j = 0; j < 8; j++) acc[i][j] = 0.f;

    for (int k0 = 0; k0 < K; k0 += 16) {
#pragma unroll
        for (int u = 0; u < 2; u++) {
            int f   = tid + u * 256;       // 512 float4 per tile per operand
            int row = f >> 2;
            int kc  = (f & 3) << 2;
            float4 va = *(const float4*)(A + (size_t)(m0 + row) * K + k0 + kc);
            As[kc + 0][row] = va.x; As[kc + 1][row] = va.y;
            As[kc + 2][row] = va.z; As[kc + 3][row] = va.w;
            float4 vb = *(const float4*)(W + (size_t)(n0 + row) * K + k0 + kc);
            Bs[kc + 0][row] = vb.x; Bs[kc + 1][row] = vb.y;
            Bs[kc + 2][row] = vb.z; Bs[kc + 3][row] = vb.w;
        }
        __syncthreads();
#pragma unroll
        for (int kk = 0; kk < 16; kk++) {
            float4 a0 = *(const float4*)&As[kk][ty * 8];
            float4 a1 = *(const float4*)&As[kk][ty * 8 + 4];
            float4 b0 = *(const float4*)&Bs[kk][tx * 8];
            float4 b1 = *(const float4*)&Bs[kk][tx * 8 + 4];
            float a[8] = {a0.x, a0.y, a0.z, a0.w, a1.x, a1.y, a1.z, a1.w};
            float b[8] = {b0.x, b0.y, b0.z, b0.w, b1.x, b1.y, b1.z, b1.w};
#pragma unroll
            for (int i = 0; i < 8; i++)
#pragma unroll
                for (int j = 0; j < 8; j++)
                    acc[i][j] += a[i] * b[j];
        }
        __syncthreads();
    }

#pragma unroll
    for (int i = 0; i < 8; i++) {
        int m = m0 + ty * 8 + i;
#pragma unroll
        for (int j = 0; j < 8; j++) {
            int n = n0 + tx * 8 + j;
            float v = acc[i][j] + bias[n];
            if (HEADSPLIT) {
                int h = n >> 6, d = n & 63;
                dst[((size_t)h * S_LEN + m) * HD + d] = v;
            } else {
                dst[(size_t)m * E_DIM + n] = v;
            }
        }
    }
}

// ---------------------------------------------------------------------------
// Windowed attention, flash-style online softmax.
// grid = (4 q-chunks of 128, 8 windows, 16 heads), 256 threads.
// Collected keys per window: c in [0,1536), global t = w*512 - 512 + c.
//   t out of [0,S) -> pad: k = v = -1 everywhere, NEVER masked.
//   otherwise masked unless c in [qr, qr+1024]  (qr = query offset in window).
// ---------------------------------------------------------------------------
__global__ __launch_bounds__(256)
void attn_kernel()
{
    extern __shared__ float sm[];
    float* Qs = sm;               // [64][128]  (d-major, transposed)
    float* Ks = Qs + 64 * 128;    // [64][128]
    float* Vs = Ks + 64 * 128;    // [128][64]
    float* Ps = Vs + 128 * 64;    // [128][129]

    const int tid = threadIdx.x;
    const int tx  = tid & 15, ty = tid >> 4;
    const int q0  = blockIdx.x * 128;   // query offset in window
    const int w   = blockIdx.y;
    const int h   = blockIdx.z;
    const int base = w * WSZ - WSZ;     // global t of collected index 0

    // Load Q chunk transposed: Qs[d][r]
    const float* qg = g_q + ((size_t)h * S_LEN + w * WSZ + q0) * HD;
    for (int f = tid; f < 128 * 16; f += 256) {
        int r = f >> 4, d4 = (f & 15) << 2;
        float4 v = *(const float4*)(qg + r * HD + d4);
        Qs[(d4 + 0) * 128 + r] = v.x;
        Qs[(d4 + 1) * 128 + r] = v.y;
        Qs[(d4 + 2) * 128 + r] = v.z;
        Qs[(d4 + 3) * 128 + r] = v.w;
    }

    float mrow[8], lrow[8], o[8][4];
#pragma unroll
    for (int i = 0; i < 8; i++) {
        mrow[i] = -1e30f; lrow[i] = 0.f;
#pragma unroll
        for (int j = 0; j < 4; j++) o[i][j] = 0.f;
    }

    const float* kg = g_k + (size_t)h * S_LEN * HD;
    const float* vg = g_v + (size_t)h * S_LEN * HD;

    for (int kt = 0; kt < NTILE; kt++) {
        __syncthreads();   // prev PV done; Ks/Vs free
        for (int f = tid; f < 128 * 16; f += 256) {
            int cc = f >> 4, d4 = (f & 15) << 2;
            int t = base + kt * 128 + cc;
            float4 kv, vv;
            if (t >= 0 && t < S_LEN) {
                kv = *(const float4*)(kg + (size_t)t * HD + d4);
                vv = *(const float4*)(vg + (size_t)t * HD + d4);
            } else {
                kv = make_float4(-1.f, -1.f, -1.f, -1.f);
                vv = kv;
            }
            Ks[(d4 + 0) * 128 + cc] = kv.x;
            Ks[(d4 + 1) * 128 + cc] = kv.y;
            Ks[(d4 + 2) * 128 + cc] = kv.z;
            Ks[(d4 + 3) * 128 + cc] = kv.w;
            *(float4*)(Vs + cc * HD + d4) = vv;
        }
        __syncthreads();

        // S = Q K^T for this 128x128 tile
        float s[8][8];
#pragma unroll
        for (int i = 0; i < 8; i++)
#pragma unroll
            for (int j = 0; j < 8; j++) s[i][j] = 0.f;

#pragma unroll 4
        for (int d = 0; d < HD; d++) {
            float4 a0 = *(const float4*)&Qs[d * 128 + ty * 8];
            float4 a1 = *(const float4*)&Qs[d * 128 + ty * 8 + 4];
            float4 b0 = *(const float4*)&Ks[d * 128 + tx * 8];
            float4 b1 = *(const float4*)&Ks[d * 128 + tx * 8 + 4];
            float a[8] = {a0.x, a0.y, a0.z, a0.w, a1.x, a1.y, a1.z, a1.w};
            float b[8] = {b0.x, b0.y, b0.z, b0.w, b1.x, b1.y, b1.z, b1.w};
#pragma unroll
            for (int i = 0; i < 8; i++)
#pragma unroll
                for (int j = 0; j < 8; j++)
                    s[i][j] += a[i] * b[j];
        }

        // mask
        const int cb = kt * 128 + tx * 8;
#pragma unroll
        for (int j = 0; j < 8; j++) {
            int c = cb + j;
            int t = base + c;
            bool pad = (t < 0) || (t >= S_LEN);
#pragma unroll
            for (int i = 0; i < 8; i++) {
                int qr = q0 + ty * 8 + i;
                bool ok = pad || ((c >= qr) && (c <= qr + 1024));
                if (!ok) s[i][j] = -1e30f;
            }
        }

        // online softmax update (row state replicated across the 16 tx lanes;
        // lanes (ty%2)*16 + tx -> xor 1/2/4/8 reduces across tx only)
#pragma unroll
        for (int i = 0; i < 8; i++) {
            float tm = s[i][0];
#pragma unroll
            for (int j = 1; j < 8; j++) tm = fmaxf(tm, s[i][j]);
            tm = fmaxf(tm, __shfl_xor_sync(0xffffffffu, tm, 1));
            tm = fmaxf(tm, __shfl_xor_sync(0xffffffffu, tm, 2));
            tm = fmaxf(tm, __shfl_xor_sync(0xffffffffu, tm, 4));
            tm = fmaxf(tm, __shfl_xor_sync(0xffffffffu, tm, 8));
            float nm   = fmaxf(mrow[i], tm);
            float corr = __expf(mrow[i] - nm);
            mrow[i] = nm;
            float ps = 0.f;
#pragma unroll
            for (int j = 0; j < 8; j++) {
                float p = __expf(s[i][j] - nm);
                ps += p;
                Ps[(ty * 8 + i) * 129 + tx * 8 + j] = p;
            }
            ps += __shfl_xor_sync(0xffffffffu, ps, 1);
            ps += __shfl_xor_sync(0xffffffffu, ps, 2);
            ps += __shfl_xor_sync(0xffffffffu, ps, 4);
            ps += __shfl_xor_sync(0xffffffffu, ps, 8);
            lrow[i] = lrow[i] * corr + ps;
#pragma unroll
            for (int j = 0; j < 4; j++) o[i][j] *= corr;
        }
        __syncthreads();

        // O += P V   (o[i][j]: rows ty*8+i, cols tx*4+j)
        for (int c = 0; c < 128; c++) {
            float4 v4 = *(const float4*)&Vs[c * HD + tx * 4];
            float pr[8];
#pragma unroll
            for (int i = 0; i < 8; i++) pr[i] = Ps[(ty * 8 + i) * 129 + c];
#pragma unroll
            for (int i = 0; i < 8; i++) {
                o[i][0] += pr[i] * v4.x;
                o[i][1] += pr[i] * v4.y;
                o[i][2] += pr[i] * v4.z;
                o[i][3] += pr[i] * v4.w;
            }
        }
    }

    // normalize + store in [s][e] layout for the output GEMM
#pragma unroll
    for (int i = 0; i < 8; i++) {
        int sg  = w * WSZ + q0 + ty * 8 + i;
        float inv = 1.f / lrow[i];
#pragma unroll
        for (int j = 0; j < 4; j++)
            g_att[(size_t)sg * E_DIM + h * HD + tx * 4 + j] = o[i][j] * inv;
    }
}

// ---------------------------------------------------------------------------
extern "C" void kernel_launch(void* const* d_in, const int* in_sizes, int n_in,
                              void* d_out, int out_size)
{
    const float* x  = (const float*)d_in[0];
    const float* wq = (const float*)d_in[1];
    const float* bq = (const float*)d_in[2];
    const float* wk = (const float*)d_in[3];
    const float* bk = (const float*)d_in[4];
    const float* wv = (const float*)d_in[5];
    const float* bv = (const float*)d_in[6];
    const float* wo = (const float*)d_in[7];
    const float* bo = (const float*)d_in[8];
    float* out = (float*)d_out;

    float *q, *k, *v, *att;
    cudaGetSymbolAddress((void**)&q,   g_q);
    cudaGetSymbolAddress((void**)&k,   g_k);
    cudaGetSymbolAddress((void**)&v,   g_v);
    cudaGetSymbolAddress((void**)&att, g_att);

    const int smem_bytes = (64 * 128 * 2 + 128 * 64 + 128 * 129) * 4;  // 164352
    cudaFuncSetAttribute(attn_kernel,
                         cudaFuncAttributeMaxDynamicSharedMemorySize, smem_bytes);

    dim3 gg(E_DIM / 128, S_LEN / 128);   // (8, 32)
    gemm_bias_kernel<1><<<gg, 256>>>(x, wq, bq, q);
    gemm_bias_kernel<1><<<gg, 256>>>(x, wk, bk, k);
    gemm_bias_kernel<1><<<gg, 256>>>(x, wv, bv, v);

    dim3 ga(4, 8, 16);                   // q-chunk, window, head
    attn_kernel<<<ga, 256, smem_bytes>>>();

    gemm_bias_kernel<0><<<gg, 256>>>(att, wo, bo, out);
}

// round 4
// speedup vs baseline: 1.9911x; 1.9911x over previous
#include <cuda_runtime.h>
#include <cstdint>

#define S_LEN 4096
#define E_DIM 1024
#define H_NUM 16
#define HD    64
#define WSZ   512
#define NTILE 12   // 1536 collected keys / 128

// Scratch (allocation-free rule: __device__ globals).
__device__ float g_q[H_NUM * S_LEN * HD];
__device__ float g_k[H_NUM * S_LEN * HD];
__device__ float g_v[H_NUM * S_LEN * HD];
__device__ float g_att[S_LEN * E_DIM];

// ---------------------------------------------------------------------------
// tf32 helpers
// ---------------------------------------------------------------------------
__device__ __forceinline__ uint32_t f2tf32(float x) {
    uint32_t r;
    asm("cvt.rna.tf32.f32 %0, %1;" : "=r"(r) : "f"(x));
    return r;
}
__device__ __forceinline__ void ldsm4(uint32_t& r0, uint32_t& r1, uint32_t& r2,
                                      uint32_t& r3, uint32_t addr) {
    asm volatile("ldmatrix.sync.aligned.m8n8.x4.shared.b16 {%0,%1,%2,%3}, [%4];"
                 : "=r"(r0), "=r"(r1), "=r"(r2), "=r"(r3) : "r"(addr));
}
__device__ __forceinline__ void mma_tf32(float c[4], const uint32_t a[4],
                                         uint32_t b0, uint32_t b1) {
    asm volatile(
        "mma.sync.aligned.m16n8k8.row.col.f32.tf32.tf32.f32 "
        "{%0,%1,%2,%3},{%4,%5,%6,%7},{%8,%9},{%0,%1,%2,%3};"
        : "+f"(c[0]), "+f"(c[1]), "+f"(c[2]), "+f"(c[3])
        : "r"(a[0]), "r"(a[1]), "r"(a[2]), "r"(a[3]), "r"(b0), "r"(b1));
}

// ---------------------------------------------------------------------------
// tf32 GEMM: dst = A[M,K] @ W[N,K]^T + bias[N]   (M=4096, N=K=1024)
// CTA 128x128, BK=32, 256 threads = 8 warps (2 m x 4 n), warp tile 64x32.
// HEADSPLIT=1 -> store to [h][s][d] layout (h=n>>6, d=n&63).
// ---------------------------------------------------------------------------
template<int HEADSPLIT>
__global__ __launch_bounds__(256)
void gemm_tf32_kernel(const float* __restrict__ A, const float* __restrict__ W,
                      const float* __restrict__ bias, float* __restrict__ dst)
{
    __shared__ uint32_t As[128 * 36];   // [row][k] pad->36 (conflict-free LDSM)
    __shared__ uint32_t Bs[128 * 36];   // [n][k]

    const int tid  = threadIdx.x;
    const int warp = tid >> 5, lane = tid & 31;
    const int wm = warp >> 2, wn = warp & 3;       // 2 x 4
    const int m0 = blockIdx.y * 128, n0 = blockIdx.x * 128;

    float acc[4][4][4];
#pragma unroll
    for (int i = 0; i < 4; i++)
#pragma unroll
        for (int j = 0; j < 4; j++)
#pragma unroll
            for (int r = 0; r < 4; r++) acc[i][j][r] = 0.f;

    const uint32_t as_u = (uint32_t)__cvta_generic_to_shared(As);
    const uint32_t bs_u = (uint32_t)__cvta_generic_to_shared(Bs);
    // A frag lane mapping: matrices {rows+0 k0, rows+8 k0, rows+0 k4, rows+8 k4}
    const int a_row = (lane & 7) + ((lane >> 3) & 1) * 8;
    const int a_k   = (lane >> 4) * 4;
    // B frag lane mapping: matrices {n+0 k0, n+0 k4, n+8 k0, n+8 k4}
    const int b_row = (lane & 7) + (lane >> 4) * 8;
    const int b_k   = ((lane >> 3) & 1) * 4;
    const uint32_t abase = as_u + ((wm * 64 + a_row) * 36 + a_k) * 4;
    const uint32_t bbase = bs_u + ((wn * 32 + b_row) * 36 + b_k) * 4;

    for (int k0 = 0; k0 < E_DIM; k0 += 32) {
#pragma unroll
        for (int u = 0; u < 4; u++) {
            int idx = tid + u * 256;            // 1024 float4 per operand
            int row = idx >> 3, kc = (idx & 7) << 2;
            float4 va = *(const float4*)(A + (size_t)(m0 + row) * E_DIM + k0 + kc);
            uint32_t* da = &As[row * 36 + kc];
            da[0] = f2tf32(va.x); da[1] = f2tf32(va.y);
            da[2] = f2tf32(va.z); da[3] = f2tf32(va.w);
            float4 vb = *(const float4*)(W + (size_t)(n0 + row) * E_DIM + k0 + kc);
            uint32_t* db = &Bs[row * 36 + kc];
            db[0] = f2tf32(vb.x); db[1] = f2tf32(vb.y);
            db[2] = f2tf32(vb.z); db[3] = f2tf32(vb.w);
        }
        __syncthreads();

#pragma unroll
        for (int kk = 0; kk < 4; kk++) {
            uint32_t a[4][4], b[2][4];
#pragma unroll
            for (int i = 0; i < 4; i++)
                ldsm4(a[i][0], a[i][1], a[i][2], a[i][3],
                      abase + (uint32_t)((i * 16 * 36 + kk * 8) * 4));
#pragma unroll
            for (int p = 0; p < 2; p++)
                ldsm4(b[p][0], b[p][1], b[p][2], b[p][3],
                      bbase + (uint32_t)((p * 16 * 36 + kk * 8) * 4));
#pragma unroll
            for (int i = 0; i < 4; i++)
#pragma unroll
                for (int j = 0; j < 4; j++) {
                    int p = j >> 1, off = (j & 1) * 2;
                    mma_tf32(acc[i][j], a[i], b[p][off], b[p][off + 1]);
                }
        }
        __syncthreads();
    }

#pragma unroll
    for (int i = 0; i < 4; i++) {
#pragma unroll
        for (int j = 0; j < 4; j++) {
            int row = m0 + wm * 64 + i * 16 + (lane >> 2);
            int col = n0 + wn * 32 + j * 8 + (lane & 3) * 2;
#pragma unroll
            for (int r = 0; r < 4; r++) {
                int rr = row + (r >> 1) * 8;
                int cc = col + (r & 1);
                float v = acc[i][j][r] + bias[cc];
                if (HEADSPLIT) {
                    int h = cc >> 6, d = cc & 63;
                    dst[((size_t)h * S_LEN + rr) * HD + d] = v;
                } else {
                    dst[(size_t)rr * E_DIM + cc] = v;
                }
            }
        }
    }
}

// ---------------------------------------------------------------------------
// Windowed attention, flash-style online softmax (fp32 SIMT) + tile skipping.
// grid = (4 q-chunks of 128, 8 windows, 16 heads), 256 threads.
// Collected keys per window: c in [0,1536), global t = w*512 - 512 + c.
//   t out of [0,S) -> pad: k = v = -1 everywhere, NEVER masked.
//   otherwise masked unless c in [qr, qr+1024]  (qr = query offset in window).
// ---------------------------------------------------------------------------
__global__ __launch_bounds__(256)
void attn_kernel()
{
    extern __shared__ float sm[];
    float* Qs = sm;               // [64][128]  (d-major, transposed)
    float* Ks = Qs + 64 * 128;    // [64][128]
    float* Vs = Ks + 64 * 128;    // [128][64]
    float* Ps = Vs + 128 * 64;    // [128][132]  (132: 16B-aligned rows)

    const int tid = threadIdx.x;
    const int tx  = tid & 15, ty = tid >> 4;
    const int q0  = blockIdx.x * 128;   // query offset in window
    const int w   = blockIdx.y;
    const int h   = blockIdx.z;
    const int base = w * WSZ - WSZ;     // global t of collected index 0

    const float* qg = g_q + ((size_t)h * S_LEN + w * WSZ + q0) * HD;
    for (int f = tid; f < 128 * 16; f += 256) {
        int r = f >> 4, d4 = (f & 15) << 2;
        float4 v = *(const float4*)(qg + r * HD + d4);
        Qs[(d4 + 0) * 128 + r] = v.x;
        Qs[(d4 + 1) * 128 + r] = v.y;
        Qs[(d4 + 2) * 128 + r] = v.z;
        Qs[(d4 + 3) * 128 + r] = v.w;
    }

    float mrow[8], lrow[8], o[8][4];
#pragma unroll
    for (int i = 0; i < 8; i++) {
        mrow[i] = -1e30f; lrow[i] = 0.f;
#pragma unroll
        for (int j = 0; j < 4; j++) o[i][j] = 0.f;
    }

    const float* kg = g_k + (size_t)h * S_LEN * HD;
    const float* vg = g_v + (size_t)h * S_LEN * HD;

    for (int kt = 0; kt < NTILE; kt++) {
        // Skip tiles that are fully masked: no pads (pads are never masked)
        // and no (c, qr) pair with c in [qr, qr+1024].
        const int c0 = kt * 128;
        bool haspad = (base + c0 < 0) || (base + c0 + 127 >= S_LEN);
        bool anyvalid = (c0 + 127 >= q0) && (c0 <= q0 + 127 + 1024);
        if (!haspad && !anyvalid) continue;

        __syncthreads();   // prev PV done; Ks/Vs free
        for (int f = tid; f < 128 * 16; f += 256) {
            int cc = f >> 4, d4 = (f & 15) << 2;
            int t = base + c0 + cc;
            float4 kv, vv;
            if (t >= 0 && t < S_LEN) {
                kv = *(const float4*)(kg + (size_t)t * HD + d4);
                vv = *(const float4*)(vg + (size_t)t * HD + d4);
            } else {
                kv = make_float4(-1.f, -1.f, -1.f, -1.f);
                vv = kv;
            }
            Ks[(d4 + 0) * 128 + cc] = kv.x;
            Ks[(d4 + 1) * 128 + cc] = kv.y;
            Ks[(d4 + 2) * 128 + cc] = kv.z;
            Ks[(d4 + 3) * 128 + cc] = kv.w;
            *(float4*)(Vs + cc * HD + d4) = vv;
        }
        __syncthreads();

        // S = Q K^T for this 128x128 tile
        float s[8][8];
#pragma unroll
        for (int i = 0; i < 8; i++)
#pragma unroll
            for (int j = 0; j < 8; j++) s[i][j] = 0.f;

#pragma unroll 4
        for (int d = 0; d < HD; d++) {
            float4 a0 = *(const float4*)&Qs[d * 128 + ty * 8];
            float4 a1 = *(const float4*)&Qs[d * 128 + ty * 8 + 4];
            float4 b0 = *(const float4*)&Ks[d * 128 + tx * 8];
            float4 b1 = *(const float4*)&Ks[d * 128 + tx * 8 + 4];
            float a[8] = {a0.x, a0.y, a0.z, a0.w, a1.x, a1.y, a1.z, a1.w};
            float b[8] = {b0.x, b0.y, b0.z, b0.w, b1.x, b1.y, b1.z, b1.w};
#pragma unroll
            for (int i = 0; i < 8; i++)
#pragma unroll
                for (int j = 0; j < 8; j++)
                    s[i][j] += a[i] * b[j];
        }

        // mask
        const int cb = c0 + tx * 8;
#pragma unroll
        for (int j = 0; j < 8; j++) {
            int c = cb + j;
            int t = base + c;
            bool pad = (t < 0) || (t >= S_LEN);
#pragma unroll
            for (int i = 0; i < 8; i++) {
                int qr = q0 + ty * 8 + i;
                bool ok = pad || ((c >= qr) && (c <= qr + 1024));
                if (!ok) s[i][j] = -1e30f;
            }
        }

        // online softmax update (row state replicated across 16 tx lanes)
#pragma unroll
        for (int i = 0; i < 8; i++) {
            float tm = s[i][0];
#pragma unroll
            for (int j = 1; j < 8; j++) tm = fmaxf(tm, s[i][j]);
            tm = fmaxf(tm, __shfl_xor_sync(0xffffffffu, tm, 1));
            tm = fmaxf(tm, __shfl_xor_sync(0xffffffffu, tm, 2));
            tm = fmaxf(tm, __shfl_xor_sync(0xffffffffu, tm, 4));
            tm = fmaxf(tm, __shfl_xor_sync(0xffffffffu, tm, 8));
            float nm   = fmaxf(mrow[i], tm);
            float corr = __expf(mrow[i] - nm);
            mrow[i] = nm;
            float ps = 0.f;
#pragma unroll
            for (int j = 0; j < 8; j++) {
                float p = __expf(s[i][j] - nm);
                ps += p;
                Ps[(ty * 8 + i) * 132 + tx * 8 + j] = p;
            }
            ps += __shfl_xor_sync(0xffffffffu, ps, 1);
            ps += __shfl_xor_sync(0xffffffffu, ps, 2);
            ps += __shfl_xor_sync(0xffffffffu, ps, 4);
            ps += __shfl_xor_sync(0xffffffffu, ps, 8);
            lrow[i] = lrow[i] * corr + ps;
#pragma unroll
            for (int j = 0; j < 4; j++) o[i][j] *= corr;
        }
        __syncthreads();

        // O += P V   (vectorized P loads: rows of Ps are contiguous in c)
        for (int c = 0; c < 128; c += 4) {
            float4 p4[8];
#pragma unroll
            for (int i = 0; i < 8; i++)
                p4[i] = *(const float4*)&Ps[(ty * 8 + i) * 132 + c];
#pragma unroll
            for (int cc = 0; cc < 4; cc++) {
                float4 v4 = *(const float4*)&Vs[(c + cc) * HD + tx * 4];
#pragma unroll
                for (int i = 0; i < 8; i++) {
                    float p = (cc == 0) ? p4[i].x : (cc == 1) ? p4[i].y
                             : (cc == 2) ? p4[i].z : p4[i].w;
                    o[i][0] += p * v4.x;
                    o[i][1] += p * v4.y;
                    o[i][2] += p * v4.z;
                    o[i][3] += p * v4.w;
                }
            }
        }
    }

    // normalize + store in [s][e] layout for the output GEMM
#pragma unroll
    for (int i = 0; i < 8; i++) {
        int sg  = w * WSZ + q0 + ty * 8 + i;
        float inv = 1.f / lrow[i];
#pragma unroll
        for (int j = 0; j < 4; j++)
            g_att[(size_t)sg * E_DIM + h * HD + tx * 4 + j] = o[i][j] * inv;
    }
}

// ---------------------------------------------------------------------------
extern "C" void kernel_launch(void* const* d_in, const int* in_sizes, int n_in,
                              void* d_out, int out_size)
{
    const float* x  = (const float*)d_in[0];
    const float* wq = (const float*)d_in[1];
    const float* bq = (const float*)d_in[2];
    const float* wk = (const float*)d_in[3];
    const float* bk = (const float*)d_in[4];
    const float* wv = (const float*)d_in[5];
    const float* bv = (const float*)d_in[6];
    const float* wo = (const float*)d_in[7];
    const float* bo = (const float*)d_in[8];
    float* out = (float*)d_out;

    float *q, *k, *v, *att;
    cudaGetSymbolAddress((void**)&q,   g_q);
    cudaGetSymbolAddress((void**)&k,   g_k);
    cudaGetSymbolAddress((void**)&v,   g_v);
    cudaGetSymbolAddress((void**)&att, g_att);

    const int smem_bytes = (64 * 128 * 2 + 128 * 64 + 128 * 132) * 4;  // 165888
    cudaFuncSetAttribute(attn_kernel,
                         cudaFuncAttributeMaxDynamicSharedMemorySize, smem_bytes);

    dim3 gg(E_DIM / 128, S_LEN / 128);   // (8, 32)
    gemm_tf32_kernel<1><<<gg, 256>>>(x, wq, bq, q);
    gemm_tf32_kernel<1><<<gg, 256>>>(x, wk, bk, k);
    gemm_tf32_kernel<1><<<gg, 256>>>(x, wv, bv, v);

    dim3 ga(4, 8, 16);                   // q-chunk, window, head
    attn_kernel<<<ga, 256, smem_bytes>>>();

    gemm_tf32_kernel<0><<<gg, 256>>>(att, wo, bo, out);
}

// round 5
// speedup vs baseline: 3.1752x; 1.5947x over previous
#include <cuda_runtime.h>
#include <cuda_bf16.h>
#include <cstdint>

#define S_LEN 4096
#define E_DIM 1024
#define H_NUM 16
#define HD    64
#define WSZ   512
#define NTILE 12   // 1536 collected keys / 128

// Scratch (allocation-free rule: __device__ globals).
__device__ float g_q[H_NUM * S_LEN * HD];
__device__ float g_k[H_NUM * S_LEN * HD];
__device__ float g_v[H_NUM * S_LEN * HD];
__device__ float g_att[S_LEN * E_DIM];

// ---------------------------------------------------------------------------
// helpers
// ---------------------------------------------------------------------------
__device__ __forceinline__ uint32_t f2tf32(float x) {
    uint32_t r;
    asm("cvt.rna.tf32.f32 %0, %1;" : "=r"(r) : "f"(x));
    return r;
}
__device__ __forceinline__ void ldsm4(uint32_t& r0, uint32_t& r1, uint32_t& r2,
                                      uint32_t& r3, uint32_t addr) {
    asm volatile("ldmatrix.sync.aligned.m8n8.x4.shared.b16 {%0,%1,%2,%3}, [%4];"
                 : "=r"(r0), "=r"(r1), "=r"(r2), "=r"(r3) : "r"(addr));
}
__device__ __forceinline__ void ldsm4t(uint32_t& r0, uint32_t& r1, uint32_t& r2,
                                       uint32_t& r3, uint32_t addr) {
    asm volatile("ldmatrix.sync.aligned.m8n8.x4.trans.shared.b16 {%0,%1,%2,%3}, [%4];"
                 : "=r"(r0), "=r"(r1), "=r"(r2), "=r"(r3) : "r"(addr));
}
__device__ __forceinline__ void mma_tf32(float c[4], const uint32_t a[4],
                                         uint32_t b0, uint32_t b1) {
    asm volatile(
        "mma.sync.aligned.m16n8k8.row.col.f32.tf32.tf32.f32 "
        "{%0,%1,%2,%3},{%4,%5,%6,%7},{%8,%9},{%0,%1,%2,%3};"
        : "+f"(c[0]), "+f"(c[1]), "+f"(c[2]), "+f"(c[3])
        : "r"(a[0]), "r"(a[1]), "r"(a[2]), "r"(a[3]), "r"(b0), "r"(b1));
}
__device__ __forceinline__ void mma_bf16(float c[4],
                                         uint32_t a0, uint32_t a1, uint32_t a2, uint32_t a3,
                                         uint32_t b0, uint32_t b1) {
    asm volatile(
        "mma.sync.aligned.m16n8k16.row.col.f32.bf16.bf16.f32 "
        "{%0,%1,%2,%3},{%4,%5,%6,%7},{%8,%9},{%0,%1,%2,%3};"
        : "+f"(c[0]), "+f"(c[1]), "+f"(c[2]), "+f"(c[3])
        : "r"(a0), "r"(a1), "r"(a2), "r"(a3), "r"(b0), "r"(b1));
}
// pack two floats -> bf16x2 (lo = x0, hi = x1)
__device__ __forceinline__ uint32_t pack_bf2(float x0, float x1) {
    uint32_t r;
    asm("cvt.rn.bf16x2.f32 %0, %1, %2;" : "=r"(r) : "f"(x1), "f"(x0));
    return r;
}
// split float4 into bf16 hi/lo packed pairs
__device__ __forceinline__ void split4(float4 v, uint32_t& h01, uint32_t& h23,
                                       uint32_t& l01, uint32_t& l23) {
    h01 = pack_bf2(v.x, v.y);
    h23 = pack_bf2(v.z, v.w);
    float f0 = __uint_as_float(h01 << 16);
    float f1 = __uint_as_float(h01 & 0xffff0000u);
    float f2 = __uint_as_float(h23 << 16);
    float f3 = __uint_as_float(h23 & 0xffff0000u);
    l01 = pack_bf2(v.x - f0, v.y - f1);
    l23 = pack_bf2(v.z - f2, v.w - f3);
}
// split a float pair into hi/lo packed bf16x2
__device__ __forceinline__ void split2(float x0, float x1, uint32_t& h, uint32_t& l) {
    h = pack_bf2(x0, x1);
    float f0 = __uint_as_float(h << 16);
    float f1 = __uint_as_float(h & 0xffff0000u);
    l = pack_bf2(x0 - f0, x1 - f1);
}

// ---------------------------------------------------------------------------
// tf32 GEMM: dst = A[M,K] @ W[N,K]^T + bias[N]   (unchanged from R2)
// ---------------------------------------------------------------------------
template<int HEADSPLIT>
__global__ __launch_bounds__(256)
void gemm_tf32_kernel(const float* __restrict__ A, const float* __restrict__ W,
                      const float* __restrict__ bias, float* __restrict__ dst)
{
    __shared__ uint32_t As[128 * 36];
    __shared__ uint32_t Bs[128 * 36];

    const int tid  = threadIdx.x;
    const int warp = tid >> 5, lane = tid & 31;
    const int wm = warp >> 2, wn = warp & 3;
    const int m0 = blockIdx.y * 128, n0 = blockIdx.x * 128;

    float acc[4][4][4];
#pragma unroll
    for (int i = 0; i < 4; i++)
#pragma unroll
        for (int j = 0; j < 4; j++)
#pragma unroll
            for (int r = 0; r < 4; r++) acc[i][j][r] = 0.f;

    const uint32_t as_u = (uint32_t)__cvta_generic_to_shared(As);
    const uint32_t bs_u = (uint32_t)__cvta_generic_to_shared(Bs);
    const int a_row = (lane & 7) + ((lane >> 3) & 1) * 8;
    const int a_k   = (lane >> 4) * 4;
    const int b_row = (lane & 7) + (lane >> 4) * 8;
    const int b_k   = ((lane >> 3) & 1) * 4;
    const uint32_t abase = as_u + ((wm * 64 + a_row) * 36 + a_k) * 4;
    const uint32_t bbase = bs_u + ((wn * 32 + b_row) * 36 + b_k) * 4;

    for (int k0 = 0; k0 < E_DIM; k0 += 32) {
#pragma unroll
        for (int u = 0; u < 4; u++) {
            int idx = tid + u * 256;
            int row = idx >> 3, kc = (idx & 7) << 2;
            float4 va = *(const float4*)(A + (size_t)(m0 + row) * E_DIM + k0 + kc);
            uint32_t* da = &As[row * 36 + kc];
            da[0] = f2tf32(va.x); da[1] = f2tf32(va.y);
            da[2] = f2tf32(va.z); da[3] = f2tf32(va.w);
            float4 vb = *(const float4*)(W + (size_t)(n0 + row) * E_DIM + k0 + kc);
            uint32_t* db = &Bs[row * 36 + kc];
            db[0] = f2tf32(vb.x); db[1] = f2tf32(vb.y);
            db[2] = f2tf32(vb.z); db[3] = f2tf32(vb.w);
        }
        __syncthreads();

#pragma unroll
        for (int kk = 0; kk < 4; kk++) {
            uint32_t a[4][4], b[2][4];
#pragma unroll
            for (int i = 0; i < 4; i++)
                ldsm4(a[i][0], a[i][1], a[i][2], a[i][3],
                      abase + (uint32_t)((i * 16 * 36 + kk * 8) * 4));
#pragma unroll
            for (int p = 0; p < 2; p++)
                ldsm4(b[p][0], b[p][1], b[p][2], b[p][3],
                      bbase + (uint32_t)((p * 16 * 36 + kk * 8) * 4));
#pragma unroll
            for (int i = 0; i < 4; i++)
#pragma unroll
                for (int j = 0; j < 4; j++) {
                    int p = j >> 1, off = (j & 1) * 2;
                    mma_tf32(acc[i][j], a[i], b[p][off], b[p][off + 1]);
                }
        }
        __syncthreads();
    }

#pragma unroll
    for (int i = 0; i < 4; i++) {
#pragma unroll
        for (int j = 0; j < 4; j++) {
            int row = m0 + wm * 64 + i * 16 + (lane >> 2);
            int col = n0 + wn * 32 + j * 8 + (lane & 3) * 2;
#pragma unroll
            for (int r = 0; r < 4; r++) {
                int rr = row + (r >> 1) * 8;
                int cc = col + (r & 1);
                float v = acc[i][j][r] + bias[cc];
                if (HEADSPLIT) {
                    int h = cc >> 6, d = cc & 63;
                    dst[((size_t)h * S_LEN + rr) * HD + d] = v;
                } else {
                    dst[(size_t)rr * E_DIM + cc] = v;
                }
            }
        }
    }
}

// ---------------------------------------------------------------------------
// Windowed attention via bf16x2-split tensor-core MMA (3 passes = ~fp32).
// grid = (4 q-chunks of 128, 8 windows, 16 heads), 256 threads = 8 warps.
// Each warp owns 16 query rows. K tiles of 128 keys, skip fully-masked tiles.
// smem (bf16, row stride 72): Qhi Qlo Khi Klo Vhi Vlo, each 128x72.
// ---------------------------------------------------------------------------
#define RS   72                    // b16 row stride (conflict-free ldmatrix)
#define REG  (128 * RS * 2)        // 18432 bytes per region
__global__ __launch_bounds__(256)
void attn_kernel()
{
    extern __shared__ char smc[];
    const uint32_t smu = (uint32_t)__cvta_generic_to_shared(smc);
    const uint32_t QHI = smu, QLO = smu + REG;
    const uint32_t KHI = smu + 2 * REG, KLO = smu + 3 * REG;
    const uint32_t VHI = smu + 4 * REG, VLO = smu + 5 * REG;
    uint2* smQh = (uint2*)(smc);
    uint2* smQl = (uint2*)(smc + REG);
    uint2* smKh = (uint2*)(smc + 2 * REG);
    uint2* smKl = (uint2*)(smc + 3 * REG);
    uint2* smVh = (uint2*)(smc + 4 * REG);
    uint2* smVl = (uint2*)(smc + 5 * REG);

    const int tid  = threadIdx.x;
    const int warp = tid >> 5, lane = tid & 31;
    const int q0   = blockIdx.x * 128;
    const int w    = blockIdx.y;
    const int h    = blockIdx.z;
    const int base = w * WSZ - WSZ;

    // ldmatrix per-lane byte offsets
    const uint32_t a_lane = (uint32_t)(((warp * 16 + (lane & 7) + ((lane >> 3) & 1) * 8) * RS
                                        + (lane >> 4) * 8) * 2);
    const uint32_t kb_lane = (uint32_t)((((lane & 7) + ((lane >> 3) & 1) * 8) * RS
                                        + (lane >> 4) * 8) * 2);
    const uint32_t vb_lane = (uint32_t)((((lane & 7) + ((lane >> 4) & 1) * 8) * RS
                                        + ((lane >> 3) & 1) * 8) * 2);

    // ---- load Q chunk, split to bf16 hi/lo ----
    const float* qg = g_q + ((size_t)h * S_LEN + w * WSZ + q0) * HD;
    for (int f = tid; f < 128 * 16; f += 256) {
        int r = f >> 4, c4 = f & 15;
        float4 v = *(const float4*)(qg + r * HD + c4 * 4);
        uint32_t h01, h23, l01, l23;
        split4(v, h01, h23, l01, l23);
        smQh[r * 18 + c4] = make_uint2(h01, h23);
        smQl[r * 18 + c4] = make_uint2(l01, l23);
    }

    const float* kg = g_k + (size_t)h * S_LEN * HD;
    const float* vg = g_v + (size_t)h * S_LEN * HD;

    float m0r = -1e30f, m1r = -1e30f, l0r = 0.f, l1r = 0.f;
    float o[8][4];
#pragma unroll
    for (int f = 0; f < 8; f++)
#pragma unroll
        for (int e = 0; e < 4; e++) o[f][e] = 0.f;

    const int r0 = q0 + warp * 16 + (lane >> 2);
    const int r1 = r0 + 8;

    for (int kt = 0; kt < NTILE; kt++) {
        const int c0 = kt * 128;
        bool haspad = (base + c0 < 0) || (base + c0 + 127 >= S_LEN);
        bool anyvalid = (c0 + 127 >= q0) && (c0 <= q0 + 127 + 1024);
        if (!haspad && !anyvalid) continue;

        __syncthreads();   // previous tile's MMA reads done
        for (int f = tid; f < 128 * 16; f += 256) {
            int r = f >> 4, c4 = f & 15;
            int t = base + c0 + r;
            uint32_t h01, h23, l01, l23, vh01, vh23, vl01, vl23;
            if (t >= 0 && t < S_LEN) {
                float4 kv = *(const float4*)(kg + (size_t)t * HD + c4 * 4);
                float4 vv = *(const float4*)(vg + (size_t)t * HD + c4 * 4);
                split4(kv, h01, h23, l01, l23);
                split4(vv, vh01, vh23, vl01, vl23);
            } else {
                h01 = h23 = vh01 = vh23 = 0xBF80BF80u;   // bf16 -1.0 pair
                l01 = l23 = vl01 = vl23 = 0u;
            }
            smKh[r * 18 + c4] = make_uint2(h01, h23);
            smKl[r * 18 + c4] = make_uint2(l01, l23);
            smVh[r * 18 + c4] = make_uint2(vh01, vh23);
            smVl[r * 18 + c4] = make_uint2(vl01, vl23);
        }
        __syncthreads();

        // ---- S = Q K^T (bf16x2 split, 3 passes) ----
        float sS[16][4];
#pragma unroll
        for (int f = 0; f < 16; f++)
#pragma unroll
            for (int e = 0; e < 4; e++) sS[f][e] = 0.f;

#pragma unroll
        for (int s = 0; s < 4; s++) {
            uint32_t ah0, ah1, ah2, ah3, al0, al1, al2, al3;
            ldsm4(ah0, ah1, ah2, ah3, QHI + a_lane + s * 32);
            ldsm4(al0, al1, al2, al3, QLO + a_lane + s * 32);
#pragma unroll
            for (int p = 0; p < 8; p++) {
                uint32_t bh0, bh1, bh2, bh3, bl0, bl1, bl2, bl3;
                ldsm4(bh0, bh1, bh2, bh3, KHI + kb_lane + p * 2304 + s * 32);
                ldsm4(bl0, bl1, bl2, bl3, KLO + kb_lane + p * 2304 + s * 32);
                mma_bf16(sS[2*p],   ah0, ah1, ah2, ah3, bh0, bh2);
                mma_bf16(sS[2*p+1], ah0, ah1, ah2, ah3, bh1, bh3);
                mma_bf16(sS[2*p],   ah0, ah1, ah2, ah3, bl0, bl2);
                mma_bf16(sS[2*p+1], ah0, ah1, ah2, ah3, bl1, bl3);
                mma_bf16(sS[2*p],   al0, al1, al2, al3, bh0, bh2);
                mma_bf16(sS[2*p+1], al0, al1, al2, al3, bh1, bh3);
            }
        }

        // ---- mask ----
#pragma unroll
        for (int f = 0; f < 16; f++) {
            int c = c0 + f * 8 + (lane & 3) * 2;
#pragma unroll
            for (int e = 0; e < 2; e++) {
                int cc = c + e;
                int t = base + cc;
                bool pad = (t < 0) || (t >= S_LEN);
                if (!(pad || (cc >= r0 && cc <= r0 + 1024))) sS[f][e]     = -1e30f;
                if (!(pad || (cc >= r1 && cc <= r1 + 1024))) sS[f][2 + e] = -1e30f;
            }
        }

        // ---- row max + rescale ----
        float tm0 = -1e30f, tm1 = -1e30f;
#pragma unroll
        for (int f = 0; f < 16; f++) {
            tm0 = fmaxf(tm0, fmaxf(sS[f][0], sS[f][1]));
            tm1 = fmaxf(tm1, fmaxf(sS[f][2], sS[f][3]));
        }
        tm0 = fmaxf(tm0, __shfl_xor_sync(0xffffffffu, tm0, 1));
        tm0 = fmaxf(tm0, __shfl_xor_sync(0xffffffffu, tm0, 2));
        tm1 = fmaxf(tm1, __shfl_xor_sync(0xffffffffu, tm1, 1));
        tm1 = fmaxf(tm1, __shfl_xor_sync(0xffffffffu, tm1, 2));
        float nm0 = fmaxf(m0r, tm0), nm1 = fmaxf(m1r, tm1);
        float cr0 = __expf(m0r - nm0), cr1 = __expf(m1r - nm1);
        m0r = nm0; m1r = nm1;
#pragma unroll
        for (int f = 0; f < 8; f++) {
            o[f][0] *= cr0; o[f][1] *= cr0;
            o[f][2] *= cr1; o[f][3] *= cr1;
        }
        float la0 = 0.f, la1 = 0.f;

        // ---- P V (exp fused in, bf16x2 split, 3 passes) ----
#pragma unroll
        for (int s2 = 0; s2 < 8; s2++) {
            int f0 = 2 * s2, f1 = f0 + 1;
            float p00 = __expf(sS[f0][0] - m0r), p01 = __expf(sS[f0][1] - m0r);
            float p02 = __expf(sS[f0][2] - m1r), p03 = __expf(sS[f0][3] - m1r);
            float p10 = __expf(sS[f1][0] - m0r), p11 = __expf(sS[f1][1] - m0r);
            float p12 = __expf(sS[f1][2] - m1r), p13 = __expf(sS[f1][3] - m1r);
            la0 += p00 + p01 + p10 + p11;
            la1 += p02 + p03 + p12 + p13;
            uint32_t ah0, ah1, ah2, ah3, al0, al1, al2, al3;
            split2(p00, p01, ah0, al0);
            split2(p02, p03, ah1, al1);
            split2(p10, p11, ah2, al2);
            split2(p12, p13, ah3, al3);
#pragma unroll
            for (int q = 0; q < 4; q++) {
                uint32_t bh0, bh1, bh2, bh3, bl0, bl1, bl2, bl3;
                ldsm4t(bh0, bh1, bh2, bh3, VHI + vb_lane + s2 * 2304 + q * 32);
                ldsm4t(bl0, bl1, bl2, bl3, VLO + vb_lane + s2 * 2304 + q * 32);
                mma_bf16(o[2*q],   ah0, ah1, ah2, ah3, bh0, bh2);
                mma_bf16(o[2*q+1], ah0, ah1, ah2, ah3, bh1, bh3);
                mma_bf16(o[2*q],   ah0, ah1, ah2, ah3, bl0, bl2);
                mma_bf16(o[2*q+1], ah0, ah1, ah2, ah3, bl1, bl3);
                mma_bf16(o[2*q],   al0, al1, al2, al3, bh0, bh2);
                mma_bf16(o[2*q+1], al0, al1, al2, al3, bh1, bh3);
            }
        }
        la0 += __shfl_xor_sync(0xffffffffu, la0, 1);
        la0 += __shfl_xor_sync(0xffffffffu, la0, 2);
        la1 += __shfl_xor_sync(0xffffffffu, la1, 1);
        la1 += __shfl_xor_sync(0xffffffffu, la1, 2);
        l0r = l0r * cr0 + la0;
        l1r = l1r * cr1 + la1;
    }

    // ---- normalize + store ----
    const float i0 = 1.f / l0r, i1 = 1.f / l1r;
    const int sg0 = w * WSZ + q0 + warp * 16 + (lane >> 2);
    float* dst0 = g_att + (size_t)sg0 * E_DIM + h * HD + (lane & 3) * 2;
    float* dst1 = dst0 + 8 * E_DIM;
#pragma unroll
    for (int f = 0; f < 8; f++) {
        *(float2*)(dst0 + f * 8) = make_float2(o[f][0] * i0, o[f][1] * i0);
        *(float2*)(dst1 + f * 8) = make_float2(o[f][2] * i1, o[f][3] * i1);
    }
}

// ---------------------------------------------------------------------------
extern "C" void kernel_launch(void* const* d_in, const int* in_sizes, int n_in,
                              void* d_out, int out_size)
{
    const float* x  = (const float*)d_in[0];
    const float* wq = (const float*)d_in[1];
    const float* bq = (const float*)d_in[2];
    const float* wk = (const float*)d_in[3];
    const float* bk = (const float*)d_in[4];
    const float* wv = (const float*)d_in[5];
    const float* bv = (const float*)d_in[6];
    const float* wo = (const float*)d_in[7];
    const float* bo = (const float*)d_in[8];
    float* out = (float*)d_out;

    float *q, *k, *v, *att;
    cudaGetSymbolAddress((void**)&q,   g_q);
    cudaGetSymbolAddress((void**)&k,   g_k);
    cudaGetSymbolAddress((void**)&v,   g_v);
    cudaGetSymbolAddress((void**)&att, g_att);

    const int smem_bytes = 6 * REG;   // 110592
    cudaFuncSetAttribute(attn_kernel,
                         cudaFuncAttributeMaxDynamicSharedMemorySize, smem_bytes);

    dim3 gg(E_DIM / 128, S_LEN / 128);
    gemm_tf32_kernel<1><<<gg, 256>>>(x, wq, bq, q);
    gemm_tf32_kernel<1><<<gg, 256>>>(x, wk, bk, k);
    gemm_tf32_kernel<1><<<gg, 256>>>(x, wv, bv, v);

    dim3 ga(4, 8, 16);
    attn_kernel<<<ga, 256, smem_bytes>>>();

    gemm_tf32_kernel<0><<<gg, 256>>>(att, wo, bo, out);
}

// round 7
// speedup vs baseline: 3.7172x; 1.1707x over previous
#include <cuda_runtime.h>
#include <cuda_bf16.h>
#include <cstdint>

#define S_LEN 4096
#define E_DIM 1024
#define H_NUM 16
#define HD    64
#define WSZ   512
#define NTILE 12   // 1536 collected keys / 128

// Scratch (allocation-free rule: __device__ globals).
// Q/K/V stored as split bf16 planes (hi + lo), [h][s][d].
#define PLANE (H_NUM * S_LEN * HD)
__device__ __nv_bfloat16 g_qh[PLANE], g_ql[PLANE];
__device__ __nv_bfloat16 g_kh[PLANE], g_kl[PLANE];
__device__ __nv_bfloat16 g_vh[PLANE], g_vl[PLANE];
__device__ float g_att[S_LEN * E_DIM];

// ---------------------------------------------------------------------------
// helpers
// ---------------------------------------------------------------------------
__device__ __forceinline__ uint32_t f2tf32(float x) {
    uint32_t r;
    asm("cvt.rna.tf32.f32 %0, %1;" : "=r"(r) : "f"(x));
    return r;
}
__device__ __forceinline__ void ldsm4(uint32_t& r0, uint32_t& r1, uint32_t& r2,
                                      uint32_t& r3, uint32_t addr) {
    asm volatile("ldmatrix.sync.aligned.m8n8.x4.shared.b16 {%0,%1,%2,%3}, [%4];"
                 : "=r"(r0), "=r"(r1), "=r"(r2), "=r"(r3) : "r"(addr));
}
__device__ __forceinline__ void ldsm4t(uint32_t& r0, uint32_t& r1, uint32_t& r2,
                                       uint32_t& r3, uint32_t addr) {
    asm volatile("ldmatrix.sync.aligned.m8n8.x4.trans.shared.b16 {%0,%1,%2,%3}, [%4];"
                 : "=r"(r0), "=r"(r1), "=r"(r2), "=r"(r3) : "r"(addr));
}
__device__ __forceinline__ void mma_tf32(float c[4], const uint32_t a[4],
                                         uint32_t b0, uint32_t b1) {
    asm volatile(
        "mma.sync.aligned.m16n8k8.row.col.f32.tf32.tf32.f32 "
        "{%0,%1,%2,%3},{%4,%5,%6,%7},{%8,%9},{%0,%1,%2,%3};"
        : "+f"(c[0]), "+f"(c[1]), "+f"(c[2]), "+f"(c[3])
        : "r"(a[0]), "r"(a[1]), "r"(a[2]), "r"(a[3]), "r"(b0), "r"(b1));
}
__device__ __forceinline__ void mma_bf16(float c[4],
                                         uint32_t a0, uint32_t a1, uint32_t a2, uint32_t a3,
                                         uint32_t b0, uint32_t b1) {
    asm volatile(
        "mma.sync.aligned.m16n8k16.row.col.f32.bf16.bf16.f32 "
        "{%0,%1,%2,%3},{%4,%5,%6,%7},{%8,%9},{%0,%1,%2,%3};"
        : "+f"(c[0]), "+f"(c[1]), "+f"(c[2]), "+f"(c[3])
        : "r"(a0), "r"(a1), "r"(a2), "r"(a3), "r"(b0), "r"(b1));
}
__device__ __forceinline__ uint32_t pack_bf2(float x0, float x1) {
    uint32_t r;
    asm("cvt.rn.bf16x2.f32 %0, %1, %2;" : "=r"(r) : "f"(x1), "f"(x0));
    return r;
}
// split a float pair into hi/lo packed bf16x2
__device__ __forceinline__ void split2(float x0, float x1, uint32_t& h, uint32_t& l) {
    h = pack_bf2(x0, x1);
    float f0 = __uint_as_float(h << 16);
    float f1 = __uint_as_float(h & 0xffff0000u);
    l = pack_bf2(x0 - f0, x1 - f1);
}
__device__ __forceinline__ void cp16(uint32_t s, const void* g) {
    asm volatile("cp.async.cg.shared.global [%0], [%1], 16;" :: "r"(s), "l"(g));
}

// ---------------------------------------------------------------------------
// tf32 GEMM: dst = A[M,K] @ W[N,K]^T + bias[N]
// MODE 0: f32 output, [s][e] layout.  MODE 1: split bf16 planes, [h][s][d].
// ---------------------------------------------------------------------------
template<int MODE>
__global__ __launch_bounds__(256)
void gemm_tf32_kernel(const float* __restrict__ A, const float* __restrict__ W,
                      const float* __restrict__ bias, float* __restrict__ dst,
                      __nv_bfloat16* __restrict__ dh, __nv_bfloat16* __restrict__ dl)
{
    __shared__ uint32_t As[128 * 36];
    __shared__ uint32_t Bs[128 * 36];

    const int tid  = threadIdx.x;
    const int warp = tid >> 5, lane = tid & 31;
    const int wm = warp >> 2, wn = warp & 3;
    const int m0 = blockIdx.y * 128, n0 = blockIdx.x * 128;

    float acc[4][4][4];
#pragma unroll
    for (int i = 0; i < 4; i++)
#pragma unroll
        for (int j = 0; j < 4; j++)
#pragma unroll
            for (int r = 0; r < 4; r++) acc[i][j][r] = 0.f;

    const uint32_t as_u = (uint32_t)__cvta_generic_to_shared(As);
    const uint32_t bs_u = (uint32_t)__cvta_generic_to_shared(Bs);
    const int a_row = (lane & 7) + ((lane >> 3) & 1) * 8;
    const int a_k   = (lane >> 4) * 4;
    const int b_row = (lane & 7) + (lane >> 4) * 8;
    const int b_k   = ((lane >> 3) & 1) * 4;
    const uint32_t abase = as_u + ((wm * 64 + a_row) * 36 + a_k) * 4;
    const uint32_t bbase = bs_u + ((wn * 32 + b_row) * 36 + b_k) * 4;

    for (int k0 = 0; k0 < E_DIM; k0 += 32) {
#pragma unroll
        for (int u = 0; u < 4; u++) {
            int idx = tid + u * 256;
            int row = idx >> 3, kc = (idx & 7) << 2;
            float4 va = *(const float4*)(A + (size_t)(m0 + row) * E_DIM + k0 + kc);
            uint32_t* da = &As[row * 36 + kc];
            da[0] = f2tf32(va.x); da[1] = f2tf32(va.y);
            da[2] = f2tf32(va.z); da[3] = f2tf32(va.w);
            float4 vb = *(const float4*)(W + (size_t)(n0 + row) * E_DIM + k0 + kc);
            uint32_t* db = &Bs[row * 36 + kc];
            db[0] = f2tf32(vb.x); db[1] = f2tf32(vb.y);
            db[2] = f2tf32(vb.z); db[3] = f2tf32(vb.w);
        }
        __syncthreads();

#pragma unroll
        for (int kk = 0; kk < 4; kk++) {
            uint32_t a[4][4], b[2][4];
#pragma unroll
            for (int i = 0; i < 4; i++)
                ldsm4(a[i][0], a[i][1], a[i][2], a[i][3],
                      abase + (uint32_t)((i * 16 * 36 + kk * 8) * 4));
#pragma unroll
            for (int p = 0; p < 2; p++)
                ldsm4(b[p][0], b[p][1], b[p][2], b[p][3],
                      bbase + (uint32_t)((p * 16 * 36 + kk * 8) * 4));
#pragma unroll
            for (int i = 0; i < 4; i++)
#pragma unroll
                for (int j = 0; j < 4; j++) {
                    int p = j >> 1, off = (j & 1) * 2;
                    mma_tf32(acc[i][j], a[i], b[p][off], b[p][off + 1]);
                }
        }
        __syncthreads();
    }

#pragma unroll
    for (int i = 0; i < 4; i++) {
#pragma unroll
        for (int j = 0; j < 4; j++) {
            int row = m0 + wm * 64 + i * 16 + (lane >> 2);
            int col = n0 + wn * 32 + j * 8 + (lane & 3) * 2;
#pragma unroll
            for (int rp = 0; rp < 2; rp++) {       // row, row+8; col pair contiguous
                int rr = row + rp * 8;
                float v0 = acc[i][j][rp * 2 + 0] + bias[col];
                float v1 = acc[i][j][rp * 2 + 1] + bias[col + 1];
                if (MODE == 1) {
                    uint32_t hp, lp;
                    split2(v0, v1, hp, lp);
                    int hh = col >> 6, d = col & 63;     // d even
                    size_t off = ((size_t)hh * S_LEN + rr) * HD + d;
                    *(uint32_t*)(dh + off) = hp;
                    *(uint32_t*)(dl + off) = lp;
                } else {
                    *(float2*)(dst + (size_t)rr * E_DIM + col) = make_float2(v0, v1);
                }
            }
        }
    }
}

// ---------------------------------------------------------------------------
// Windowed attention: bf16x2-split tensor MMA, cp.async double-buffered K/V,
// closed-form pad tiles (pads are always full 128-tiles: base+c0 ≡ 0 mod 128).
// grid = (4 q-chunks of 128, 8 windows, 16 heads), 256 threads = 8 warps.
// smem: Qhi Qlo | 2 x (Khi Klo Vhi Vlo), each 128 rows x 144B (stride 72 b16).
// ---------------------------------------------------------------------------
#define RS   72
#define REG  (128 * RS * 2)        // 18432 bytes per plane
__global__ __launch_bounds__(256)
void attn_kernel()
{
    extern __shared__ char smc[];
    const uint32_t smu = (uint32_t)__cvta_generic_to_shared(smc);
    const uint32_t QHI = smu, QLO = smu + REG;

    const int tid  = threadIdx.x;
    const int warp = tid >> 5, lane = tid & 31;
    const int q0   = blockIdx.x * 128;
    const int w    = blockIdx.y;
    const int h    = blockIdx.z;
    const int base = w * WSZ - WSZ;

    const uint32_t a_lane = (uint32_t)(((warp * 16 + (lane & 7) + ((lane >> 3) & 1) * 8) * RS
                                        + (lane >> 4) * 8) * 2);
    const uint32_t kb_lane = (uint32_t)((((lane & 7) + ((lane >> 3) & 1) * 8) * RS
                                        + (lane >> 4) * 8) * 2);
    const uint32_t vb_lane = (uint32_t)((((lane & 7) + ((lane >> 4) & 1) * 8) * RS
                                        + ((lane >> 3) & 1) * 8) * 2);

    // ---- classify tiles ----
    int tiles[12], nt = 0, npad = 0;
#pragma unroll
    for (int kt = 0; kt < NTILE; kt++) {
        int c0 = kt * 128, t0 = base + c0;
        if (t0 < 0 || t0 >= S_LEN) { npad++; continue; }          // fully pad
        if ((c0 + 127 >= q0) && (c0 <= q0 + 127 + 1024)) tiles[nt++] = kt;
    }

    // ---- prologue: async-load Q planes + first two K/V tiles ----
    {
        size_t qoff = ((size_t)h * S_LEN + w * WSZ + q0) * HD;
        for (int f = tid; f < 1024; f += 256) {
            int r = f >> 3, c = f & 7;
            uint32_t so = r * 144 + c * 16;
            size_t go = qoff + (size_t)r * HD + c * 8;
            cp16(QHI + so, g_qh + go);
            cp16(QLO + so, g_ql + go);
        }
    }
    const size_t hoff = (size_t)h * S_LEN * HD;
    auto fetch = [&](int kt, int b) {
        int t0 = base + kt * 128;
        uint32_t sb = smu + (uint32_t)(2 + 4 * b) * REG;
        size_t gb = hoff + (size_t)t0 * HD;
        for (int f = tid; f < 1024; f += 256) {
            int r = f >> 3, c = f & 7;
            uint32_t so = sb + r * 144 + c * 16;
            size_t go = gb + (size_t)r * HD + c * 8;
            cp16(so,           g_kh + go);
            cp16(so + REG,     g_kl + go);
            cp16(so + 2 * REG, g_vh + go);
            cp16(so + 3 * REG, g_vl + go);
        }
    };
    fetch(tiles[0], 0);
    asm volatile("cp.async.commit_group;" ::: "memory");
    if (nt > 1) {
        fetch(tiles[1], 1);
        asm volatile("cp.async.commit_group;" ::: "memory");
    }

    float m0r = -1e30f, m1r = -1e30f, l0r = 0.f, l1r = 0.f;
    float o[8][4];
#pragma unroll
    for (int f = 0; f < 8; f++)
#pragma unroll
        for (int e = 0; e < 4; e++) o[f][e] = 0.f;

    const int r0 = q0 + warp * 16 + (lane >> 2);
    const int r1 = r0 + 8;

    for (int i = 0; i < nt; i++) {
        if (i + 1 < nt) asm volatile("cp.async.wait_group 1;" ::: "memory");
        else            asm volatile("cp.async.wait_group 0;" ::: "memory");
        __syncthreads();

        if (i == 0) {
            // qsum per owned row (Q data now resident), then closed-form pads.
            const __nv_bfloat16* qh = (const __nv_bfloat16*)smc;
            const __nv_bfloat16* ql = (const __nv_bfloat16*)(smc + REG);
            int lr0 = warp * 16 + (lane >> 2);
            float qs0 = 0.f, qs1 = 0.f;
#pragma unroll
            for (int d = 0; d < HD; d++) {
                qs0 += __bfloat162float(qh[lr0 * RS + d]) + __bfloat162float(ql[lr0 * RS + d]);
                qs1 += __bfloat162float(qh[(lr0 + 8) * RS + d]) + __bfloat162float(ql[(lr0 + 8) * RS + d]);
            }
            if (npad) {
                float s0 = -qs0, s1 = -qs1;
                float nm0 = fmaxf(m0r, s0), nm1 = fmaxf(m1r, s1);
                float cr0 = __expf(m0r - nm0), cr1 = __expf(m1r - nm1);
                m0r = nm0; m1r = nm1;
                float p0 = __expf(s0 - nm0) * (128.f * npad);
                float p1 = __expf(s1 - nm1) * (128.f * npad);
                l0r = l0r * cr0 + p0;
                l1r = l1r * cr1 + p1;
#pragma unroll
                for (int f = 0; f < 8; f++) {
                    o[f][0] = o[f][0] * cr0 - p0;
                    o[f][1] = o[f][1] * cr0 - p0;
                    o[f][2] = o[f][2] * cr1 - p1;
                    o[f][3] = o[f][3] * cr1 - p1;
                }
            }
        }

        const int kt = tiles[i];
        const int c0 = kt * 128;
        const uint32_t BB  = smu + (uint32_t)(2 + 4 * (i & 1)) * REG;
        const uint32_t KHI = BB, KLO = BB + REG, VHI = BB + 2 * REG, VLO = BB + 3 * REG;

        // ---- S = Q K^T (bf16x2 split, 3 passes) ----
        float sS[16][4];
#pragma unroll
        for (int f = 0; f < 16; f++)
#pragma unroll
            for (int e = 0; e < 4; e++) sS[f][e] = 0.f;

#pragma unroll
        for (int s = 0; s < 4; s++) {
            uint32_t ah0, ah1, ah2, ah3, al0, al1, al2, al3;
            ldsm4(ah0, ah1, ah2, ah3, QHI + a_lane + s * 32);
            ldsm4(al0, al1, al2, al3, QLO + a_lane + s * 32);
#pragma unroll
            for (int p = 0; p < 8; p++) {
                uint32_t bh0, bh1, bh2, bh3, bl0, bl1, bl2, bl3;
                ldsm4(bh0, bh1, bh2, bh3, KHI + kb_lane + p * 2304 + s * 32);
                ldsm4(bl0, bl1, bl2, bl3, KLO + kb_lane + p * 2304 + s * 32);
                mma_bf16(sS[2*p],   ah0, ah1, ah2, ah3, bh0, bh2);
                mma_bf16(sS[2*p+1], ah0, ah1, ah2, ah3, bh1, bh3);
                mma_bf16(sS[2*p],   ah0, ah1, ah2, ah3, bl0, bl2);
                mma_bf16(sS[2*p+1], ah0, ah1, ah2, ah3, bl1, bl3);
                mma_bf16(sS[2*p],   al0, al1, al2, al3, bh0, bh2);
                mma_bf16(sS[2*p+1], al0, al1, al2, al3, bh1, bh3);
            }
        }

        // ---- mask (no pads here; tiles are fully valid) ----
#pragma unroll
        for (int f = 0; f < 16; f++) {
            int c = c0 + f * 8 + (lane & 3) * 2;
#pragma unroll
            for (int e = 0; e < 2; e++) {
                int cc = c + e;
                if (!(cc >= r0 && cc <= r0 + 1024)) sS[f][e]     = -1e30f;
                if (!(cc >= r1 && cc <= r1 + 1024)) sS[f][2 + e] = -1e30f;
            }
        }

        // ---- row max + rescale ----
        float tm0 = -1e30f, tm1 = -1e30f;
#pragma unroll
        for (int f = 0; f < 16; f++) {
            tm0 = fmaxf(tm0, fmaxf(sS[f][0], sS[f][1]));
            tm1 = fmaxf(tm1, fmaxf(sS[f][2], sS[f][3]));
        }
        tm0 = fmaxf(tm0, __shfl_xor_sync(0xffffffffu, tm0, 1));
        tm0 = fmaxf(tm0, __shfl_xor_sync(0xffffffffu, tm0, 2));
        tm1 = fmaxf(tm1, __shfl_xor_sync(0xffffffffu, tm1, 1));
        tm1 = fmaxf(tm1, __shfl_xor_sync(0xffffffffu, tm1, 2));
        float nm0 = fmaxf(m0r, tm0), nm1 = fmaxf(m1r, tm1);
        float cr0 = __expf(m0r - nm0), cr1 = __expf(m1r - nm1);
        m0r = nm0; m1r = nm1;
#pragma unroll
        for (int f = 0; f < 8; f++) {
            o[f][0] *= cr0; o[f][1] *= cr0;
            o[f][2] *= cr1; o[f][3] *= cr1;
        }
        float la0 = 0.f, la1 = 0.f;

        // ---- P V (exp fused, bf16x2 split, 3 passes) ----
#pragma unroll
        for (int s2 = 0; s2 < 8; s2++) {
            int f0 = 2 * s2, f1 = f0 + 1;
            float p00 = __expf(sS[f0][0] - m0r), p01 = __expf(sS[f0][1] - m0r);
            float p02 = __expf(sS[f0][2] - m1r), p03 = __expf(sS[f0][3] - m1r);
            float p10 = __expf(sS[f1][0] - m0r), p11 = __expf(sS[f1][1] - m0r);
            float p12 = __expf(sS[f1][2] - m1r), p13 = __expf(sS[f1][3] - m1r);
            la0 += p00 + p01 + p10 + p11;
            la1 += p02 + p03 + p12 + p13;
            uint32_t ah0, ah1, ah2, ah3, al0, al1, al2, al3;
            split2(p00, p01, ah0, al0);
            split2(p02, p03, ah1, al1);
            split2(p10, p11, ah2, al2);
            split2(p12, p13, ah3, al3);
#pragma unroll
            for (int q = 0; q < 4; q++) {
                uint32_t bh0, bh1, bh2, bh3, bl0, bl1, bl2, bl3;
                ldsm4t(bh0, bh1, bh2, bh3, VHI + vb_lane + s2 * 2304 + q * 32);
                ldsm4t(bl0, bl1, bl2, bl3, VLO + vb_lane + s2 * 2304 + q * 32);
                mma_bf16(o[2*q],   ah0, ah1, ah2, ah3, bh0, bh2);
                mma_bf16(o[2*q+1], ah0, ah1, ah2, ah3, bh1, bh3);
                mma_bf16(o[2*q],   ah0, ah1, ah2, ah3, bl0, bl2);
                mma_bf16(o[2*q+1], ah0, ah1, ah2, ah3, bl1, bl3);
                mma_bf16(o[2*q],   al0, al1, al2, al3, bh0, bh2);
                mma_bf16(o[2*q+1], al0, al1, al2, al3, bh1, bh3);
            }
        }
        la0 += __shfl_xor_sync(0xffffffffu, la0, 1);
        la0 += __shfl_xor_sync(0xffffffffu, la0, 2);
        la1 += __shfl_xor_sync(0xffffffffu, la1, 1);
        la1 += __shfl_xor_sync(0xffffffffu, la1, 2);
        l0r = l0r * cr0 + la0;
        l1r = l1r * cr1 + la1;

        __syncthreads();   // all warps done reading buf i&1
        if (i + 2 < nt) {
            fetch(tiles[i + 2], i & 1);
            asm volatile("cp.async.commit_group;" ::: "memory");
        }
    }

    // ---- normalize + store ----
    const float i0 = 1.f / l0r, i1 = 1.f / l1r;
    const int sg0 = w * WSZ + q0 + warp * 16 + (lane >> 2);
    float* dst0 = g_att + (size_t)sg0 * E_DIM + h * HD + (lane & 3) * 2;
    float* dst1 = dst0 + 8 * E_DIM;
#pragma unroll
    for (int f = 0; f < 8; f++) {
        *(float2*)(dst0 + f * 8) = make_float2(o[f][0] * i0, o[f][1] * i0);
        *(float2*)(dst1 + f * 8) = make_float2(o[f][2] * i1, o[f][3] * i1);
    }
}

// ---------------------------------------------------------------------------
extern "C" void kernel_launch(void* const* d_in, const int* in_sizes, int n_in,
                              void* d_out, int out_size)
{
    const float* x  = (const float*)d_in[0];
    const float* wq = (const float*)d_in[1];
    const float* bq = (const float*)d_in[2];
    const float* wk = (const float*)d_in[3];
    const float* bk = (const float*)d_in[4];
    const float* wv = (const float*)d_in[5];
    const float* bv = (const float*)d_in[6];
    const float* wo = (const float*)d_in[7];
    const float* bo = (const float*)d_in[8];
    float* out = (float*)d_out;

    __nv_bfloat16 *qh, *ql, *kh, *kl, *vh, *vl;
    float* att;
    cudaGetSymbolAddress((void**)&qh, g_qh);
    cudaGetSymbolAddress((void**)&ql, g_ql);
    cudaGetSymbolAddress((void**)&kh, g_kh);
    cudaGetSymbolAddress((void**)&kl, g_kl);
    cudaGetSymbolAddress((void**)&vh, g_vh);
    cudaGetSymbolAddress((void**)&vl, g_vl);
    cudaGetSymbolAddress((void**)&att, g_att);

    const int smem_bytes = 10 * REG;   // 184320
    cudaFuncSetAttribute(attn_kernel,
                         cudaFuncAttributeMaxDynamicSharedMemorySize, smem_bytes);

    dim3 gg(E_DIM / 128, S_LEN / 128);
    gemm_tf32_kernel<1><<<gg, 256>>>(x, wq, bq, nullptr, qh, ql);
    gemm_tf32_kernel<1><<<gg, 256>>>(x, wk, bk, nullptr, kh, kl);
    gemm_tf32_kernel<1><<<gg, 256>>>(x, wv, bv, nullptr, vh, vl);

    dim3 ga(4, 8, 16);
    attn_kernel<<<ga, 256, smem_bytes>>>();

    gemm_tf32_kernel<0><<<gg, 256>>>(att, wo, bo, out, nullptr, nullptr);
}

// round 8
// speedup vs baseline: 4.3206x; 1.1623x over previous
#include <cuda_runtime.h>
#include <cuda_bf16.h>
#include <cuda_fp16.h>
#include <cstdint>

#define S_LEN 4096
#define E_DIM 1024
#define H_NUM 16
#define HD    64
#define WSZ   512
#define NTILE 12
#define LOG2E 1.4426950408889634f

// Scratch (allocation-free rule: __device__ globals).
#define PLANE (H_NUM * S_LEN * HD)
__device__ __nv_bfloat16 g_qh[PLANE], g_ql[PLANE];   // Q * log2(e), bf16 split
__device__ __nv_bfloat16 g_kh[PLANE], g_kl[PLANE];   // K bf16 split
__device__ __half        g_vh[PLANE], g_vl[PLANE];   // V fp16 split
__device__ float g_att[S_LEN * E_DIM];               // tf32-rounded attention out
__device__ float g_rnd[8 * 1024 * 1024];             // tf32-rounded x | wq wk wv wo

// ---------------------------------------------------------------------------
// helpers
// ---------------------------------------------------------------------------
__device__ __forceinline__ uint32_t f2tf32(float x) {
    uint32_t r;
    asm("cvt.rna.tf32.f32 %0, %1;" : "=r"(r) : "f"(x));
    return r;
}
__device__ __forceinline__ float rtf(float x) { return __uint_as_float(f2tf32(x)); }
__device__ __forceinline__ float ex2(float x) {
    float r;
    asm("ex2.approx.f32 %0, %1;" : "=f"(r) : "f"(x));
    return r;
}
__device__ __forceinline__ void ldsm4(uint32_t& r0, uint32_t& r1, uint32_t& r2,
                                      uint32_t& r3, uint32_t addr) {
    asm volatile("ldmatrix.sync.aligned.m8n8.x4.shared.b16 {%0,%1,%2,%3}, [%4];"
                 : "=r"(r0), "=r"(r1), "=r"(r2), "=r"(r3) : "r"(addr));
}
__device__ __forceinline__ void ldsm4t(uint32_t& r0, uint32_t& r1, uint32_t& r2,
                                       uint32_t& r3, uint32_t addr) {
    asm volatile("ldmatrix.sync.aligned.m8n8.x4.trans.shared.b16 {%0,%1,%2,%3}, [%4];"
                 : "=r"(r0), "=r"(r1), "=r"(r2), "=r"(r3) : "r"(addr));
}
__device__ __forceinline__ void mma_tf32(float c[4], const uint32_t a[4],
                                         uint32_t b0, uint32_t b1) {
    asm volatile(
        "mma.sync.aligned.m16n8k8.row.col.f32.tf32.tf32.f32 "
        "{%0,%1,%2,%3},{%4,%5,%6,%7},{%8,%9},{%0,%1,%2,%3};"
        : "+f"(c[0]), "+f"(c[1]), "+f"(c[2]), "+f"(c[3])
        : "r"(a[0]), "r"(a[1]), "r"(a[2]), "r"(a[3]), "r"(b0), "r"(b1));
}
__device__ __forceinline__ void mma_bf16(float c[4],
                                         uint32_t a0, uint32_t a1, uint32_t a2, uint32_t a3,
                                         uint32_t b0, uint32_t b1) {
    asm volatile(
        "mma.sync.aligned.m16n8k16.row.col.f32.bf16.bf16.f32 "
        "{%0,%1,%2,%3},{%4,%5,%6,%7},{%8,%9},{%0,%1,%2,%3};"
        : "+f"(c[0]), "+f"(c[1]), "+f"(c[2]), "+f"(c[3])
        : "r"(a0), "r"(a1), "r"(a2), "r"(a3), "r"(b0), "r"(b1));
}
__device__ __forceinline__ void mma_f16(float c[4],
                                        uint32_t a0, uint32_t a1, uint32_t a2, uint32_t a3,
                                        uint32_t b0, uint32_t b1) {
    asm volatile(
        "mma.sync.aligned.m16n8k16.row.col.f32.f16.f16.f32 "
        "{%0,%1,%2,%3},{%4,%5,%6,%7},{%8,%9},{%0,%1,%2,%3};"
        : "+f"(c[0]), "+f"(c[1]), "+f"(c[2]), "+f"(c[3])
        : "r"(a0), "r"(a1), "r"(a2), "r"(a3), "r"(b0), "r"(b1));
}
__device__ __forceinline__ uint32_t pack_bf2(float x0, float x1) {
    uint32_t r;
    asm("cvt.rn.bf16x2.f32 %0, %1, %2;" : "=r"(r) : "f"(x1), "f"(x0));
    return r;
}
__device__ __forceinline__ uint32_t pack_h2(float x0, float x1) {
    uint32_t r;
    asm("cvt.rn.f16x2.f32 %0, %1, %2;" : "=r"(r) : "f"(x1), "f"(x0));
    return r;
}
__device__ __forceinline__ void split2(float x0, float x1, uint32_t& h, uint32_t& l) {
    h = pack_bf2(x0, x1);
    float f0 = __uint_as_float(h << 16);
    float f1 = __uint_as_float(h & 0xffff0000u);
    l = pack_bf2(x0 - f0, x1 - f1);
}
__device__ __forceinline__ void split2h(float x0, float x1, uint32_t& h, uint32_t& l) {
    h = pack_h2(x0, x1);
    __half2 hv = *reinterpret_cast<__half2*>(&h);
    l = pack_h2(x0 - __half2float(hv.x), x1 - __half2float(hv.y));
}
__device__ __forceinline__ void cp16(uint32_t s, const void* g) {
    asm volatile("cp.async.cg.shared.global [%0], [%1], 16;" :: "r"(s), "l"(g));
}

// ---------------------------------------------------------------------------
// Pre-round x and the 4 weights to the tf32 grid (idempotent, into scratch).
// Layout in g_rnd (floats): [x 4M | wq 1M | wk 1M | wv 1M | wo 1M]
// ---------------------------------------------------------------------------
__global__ __launch_bounds__(256)
void preround_kernel(const float4* __restrict__ x,  const float4* __restrict__ wq,
                     const float4* __restrict__ wk, const float4* __restrict__ wv,
                     const float4* __restrict__ wo, float4* __restrict__ out)
{
    int i = blockIdx.x * 256 + threadIdx.x;          // 2M float4 total
    const float4* src;
    int j;
    if (i < (1 << 20)) { src = x; j = i; }
    else {
        int t = i - (1 << 20);
        int wsel = t >> 18;
        j = t & ((1 << 18) - 1);
        src = (wsel == 0) ? wq : (wsel == 1) ? wk : (wsel == 2) ? wv : wo;
    }
    float4 v = src[j];
    out[i] = make_float4(rtf(v.x), rtf(v.y), rtf(v.z), rtf(v.w));
}

// ---------------------------------------------------------------------------
// tf32 GEMM on pre-rounded data: dst = A[M,K] @ W[N,K]^T + bias[N]
// cp.async 2-stage pipeline, CTA 128x128, BK=32, 8 warps, warp tile 64x32.
// MODE 0: f32 out [s][e]. MODE 1: bf16 split [h][s][d] (K).
// MODE 2: bf16 split * LOG2E (Q). MODE 3: fp16 split (V).
// ---------------------------------------------------------------------------
#define GSTG 36864   // bytes per stage (A 18432 + B 18432)
template<int MODE>
__global__ __launch_bounds__(256, 2)
void gemm_tf32_kernel(const float* __restrict__ A, const float* __restrict__ W,
                      const float* __restrict__ bias, float* __restrict__ dst,
                      __nv_bfloat16* __restrict__ dh, __nv_bfloat16* __restrict__ dl,
                      __half* __restrict__ fh, __half* __restrict__ fl)
{
    extern __shared__ char smc[];
    const uint32_t smu = (uint32_t)__cvta_generic_to_shared(smc);

    const int tid  = threadIdx.x;
    const int warp = tid >> 5, lane = tid & 31;
    const int wm = warp >> 2, wn = warp & 3;
    const int m0 = blockIdx.y * 128, n0 = blockIdx.x * 128;

    float acc[4][4][4];
#pragma unroll
    for (int i = 0; i < 4; i++)
#pragma unroll
        for (int j = 0; j < 4; j++)
#pragma unroll
            for (int r = 0; r < 4; r++) acc[i][j][r] = 0.f;

    const int a_row = (lane & 7) + ((lane >> 3) & 1) * 8;
    const int a_k   = (lane >> 4) * 4;
    const int b_row = (lane & 7) + (lane >> 4) * 8;
    const int b_k   = ((lane >> 3) & 1) * 4;
    const uint32_t aoff = ((wm * 64 + a_row) * 36 + a_k) * 4;
    const uint32_t boff = 18432u + ((wn * 32 + b_row) * 36 + b_k) * 4;

    auto fetchg = [&](int k0, int st) {
        uint32_t sb = smu + (uint32_t)st * GSTG;
#pragma unroll
        for (int u = 0; u < 4; u++) {
            int f = tid + u * 256;
            int row = f >> 3, c = f & 7;
            cp16(sb + row * 144 + c * 16,
                 A + (size_t)(m0 + row) * E_DIM + k0 + c * 4);
            cp16(sb + 18432 + row * 144 + c * 16,
                 W + (size_t)(n0 + row) * E_DIM + k0 + c * 4);
        }
    };
    fetchg(0, 0);
    asm volatile("cp.async.commit_group;" ::: "memory");
    fetchg(32, 1);
    asm volatile("cp.async.commit_group;" ::: "memory");

    for (int ks = 0; ks < 32; ks++) {
        if (ks + 1 < 32) asm volatile("cp.async.wait_group 1;" ::: "memory");
        else             asm volatile("cp.async.wait_group 0;" ::: "memory");
        __syncthreads();

        const uint32_t sb = smu + (uint32_t)(ks & 1) * GSTG;
#pragma unroll
        for (int kk = 0; kk < 4; kk++) {
            uint32_t a[4][4], b[2][4];
#pragma unroll
            for (int i = 0; i < 4; i++)
                ldsm4(a[i][0], a[i][1], a[i][2], a[i][3],
                      sb + aoff + (uint32_t)((i * 16 * 36 + kk * 8) * 4));
#pragma unroll
            for (int p = 0; p < 2; p++)
                ldsm4(b[p][0], b[p][1], b[p][2], b[p][3],
                      sb + boff + (uint32_t)((p * 16 * 36 + kk * 8) * 4));
#pragma unroll
            for (int i = 0; i < 4; i++)
#pragma unroll
                for (int j = 0; j < 4; j++) {
                    int p = j >> 1, off = (j & 1) * 2;
                    mma_tf32(acc[i][j], a[i], b[p][off], b[p][off + 1]);
                }
        }
        __syncthreads();
        if (ks + 2 < 32) {
            fetchg((ks + 2) * 32, ks & 1);
            asm volatile("cp.async.commit_group;" ::: "memory");
        }
    }

#pragma unroll
    for (int i = 0; i < 4; i++) {
#pragma unroll
        for (int j = 0; j < 4; j++) {
            int row = m0 + wm * 64 + i * 16 + (lane >> 2);
            int col = n0 + wn * 32 + j * 8 + (lane & 3) * 2;
#pragma unroll
            for (int rp = 0; rp < 2; rp++) {
                int rr = row + rp * 8;
                float v0 = acc[i][j][rp * 2 + 0] + bias[col];
                float v1 = acc[i][j][rp * 2 + 1] + bias[col + 1];
                if (MODE == 0) {
                    *(float2*)(dst + (size_t)rr * E_DIM + col) = make_float2(v0, v1);
                } else {
                    int hh = col >> 6, d = col & 63;
                    size_t off = ((size_t)hh * S_LEN + rr) * HD + d;
                    if (MODE == 3) {
                        uint32_t hp, lp;
                        split2h(v0, v1, hp, lp);
                        *(uint32_t*)(fh + off) = hp;
                        *(uint32_t*)(fl + off) = lp;
                    } else {
                        if (MODE == 2) { v0 *= LOG2E; v1 *= LOG2E; }
                        uint32_t hp, lp;
                        split2(v0, v1, hp, lp);
                        *(uint32_t*)(dh + off) = hp;
                        *(uint32_t*)(dl + off) = lp;
                    }
                }
            }
        }
    }
}

// ---------------------------------------------------------------------------
// Windowed attention: QK bf16x2-split 3-pass, PV fp16 2-pass, log2-domain
// softmax (Q pre-scaled by log2e), cp.async double-buffered K/V, closed-form
// pad tiles, per-warp tile relevance + mask skipping.
// ---------------------------------------------------------------------------
#define RS   72
#define REG  (128 * RS * 2)        // 18432 bytes per plane
__global__ __launch_bounds__(256)
void attn_kernel()
{
    extern __shared__ char smc[];
    const uint32_t smu = (uint32_t)__cvta_generic_to_shared(smc);
    const uint32_t QHI = smu, QLO = smu + REG;

    const int tid  = threadIdx.x;
    const int warp = tid >> 5, lane = tid & 31;
    const int q0   = blockIdx.x * 128;
    const int w    = blockIdx.y;
    const int h    = blockIdx.z;
    const int base = w * WSZ - WSZ;
    const int Q0w  = q0 + warp * 16;        // warp's first query row (in window)

    const uint32_t a_lane = (uint32_t)(((warp * 16 + (lane & 7) + ((lane >> 3) & 1) * 8) * RS
                                        + (lane >> 4) * 8) * 2);
    const uint32_t kb_lane = (uint32_t)((((lane & 7) + ((lane >> 3) & 1) * 8) * RS
                                        + (lane >> 4) * 8) * 2);
    const uint32_t vb_lane = (uint32_t)((((lane & 7) + ((lane >> 4) & 1) * 8) * RS
                                        + ((lane >> 3) & 1) * 8) * 2);

    // ---- classify tiles ----
    int tiles[12], nt = 0, npad = 0;
#pragma unroll
    for (int kt = 0; kt < NTILE; kt++) {
        int c0 = kt * 128, t0 = base + c0;
        if (t0 < 0 || t0 >= S_LEN) { npad++; continue; }
        if ((c0 + 127 >= q0) && (c0 <= q0 + 127 + 1024)) tiles[nt++] = kt;
    }

    // ---- prologue: Q planes + first two K/V tiles ----
    {
        size_t qoff = ((size_t)h * S_LEN + w * WSZ + q0) * HD;
        for (int f = tid; f < 1024; f += 256) {
            int r = f >> 3, c = f & 7;
            uint32_t so = r * 144 + c * 16;
            size_t go = qoff + (size_t)r * HD + c * 8;
            cp16(QHI + so, g_qh + go);
            cp16(QLO + so, g_ql + go);
        }
    }
    const size_t hoff = (size_t)h * S_LEN * HD;
    auto fetch = [&](int kt, int b) {
        int t0 = base + kt * 128;
        uint32_t sb = smu + (uint32_t)(2 + 4 * b) * REG;
        size_t gb = hoff + (size_t)t0 * HD;
        for (int f = tid; f < 1024; f += 256) {
            int r = f >> 3, c = f & 7;
            uint32_t so = sb + r * 144 + c * 16;
            size_t go = gb + (size_t)r * HD + c * 8;
            cp16(so,           g_kh + go);
            cp16(so + REG,     g_kl + go);
            cp16(so + 2 * REG, g_vh + go);
            cp16(so + 3 * REG, g_vl + go);
        }
    };
    fetch(tiles[0], 0);
    asm volatile("cp.async.commit_group;" ::: "memory");
    if (nt > 1) {
        fetch(tiles[1], 1);
        asm volatile("cp.async.commit_group;" ::: "memory");
    }

    float m0r = -1e30f, m1r = -1e30f, l0r = 0.f, l1r = 0.f;
    float o[8][4];
#pragma unroll
    for (int f = 0; f < 8; f++)
#pragma unroll
        for (int e = 0; e < 4; e++) o[f][e] = 0.f;

    const int r0 = Q0w + (lane >> 2);
    const int r1 = r0 + 8;

    for (int i = 0; i < nt; i++) {
        if (i + 1 < nt) asm volatile("cp.async.wait_group 1;" ::: "memory");
        else            asm volatile("cp.async.wait_group 0;" ::: "memory");
        __syncthreads();

        if (i == 0) {
            // Closed-form pad tiles (score = -sum(q_scaled), k=v=-1, all valid).
            const __nv_bfloat16* qh = (const __nv_bfloat16*)smc;
            const __nv_bfloat16* ql = (const __nv_bfloat16*)(smc + REG);
            int lr0 = warp * 16 + (lane >> 2);
            float qs0 = 0.f, qs1 = 0.f;
#pragma unroll
            for (int d = 0; d < HD; d++) {
                qs0 += __bfloat162float(qh[lr0 * RS + d]) + __bfloat162float(ql[lr0 * RS + d]);
                qs1 += __bfloat162float(qh[(lr0 + 8) * RS + d]) + __bfloat162float(ql[(lr0 + 8) * RS + d]);
            }
            if (npad) {
                float s0 = -qs0, s1 = -qs1;
                float nm0 = fmaxf(m0r, s0), nm1 = fmaxf(m1r, s1);
                float cr0 = ex2(m0r - nm0), cr1 = ex2(m1r - nm1);
                m0r = nm0; m1r = nm1;
                float p0 = ex2(s0 - nm0) * (128.f * npad);
                float p1 = ex2(s1 - nm1) * (128.f * npad);
                l0r = l0r * cr0 + p0;
                l1r = l1r * cr1 + p1;
#pragma unroll
                for (int f = 0; f < 8; f++) {
                    o[f][0] = o[f][0] * cr0 - p0;
                    o[f][1] = o[f][1] * cr0 - p0;
                    o[f][2] = o[f][2] * cr1 - p1;
                    o[f][3] = o[f][3] * cr1 - p1;
                }
            }
        }

        const int kt = tiles[i];
        const int c0 = kt * 128;
        const bool relevant = (c0 + 127 >= Q0w) && (c0 <= Q0w + 1039);

        if (relevant) {
            const uint32_t BB  = smu + (uint32_t)(2 + 4 * (i & 1)) * REG;
            const uint32_t KHI = BB, KLO = BB + REG, VHI = BB + 2 * REG, VLO = BB + 3 * REG;

            // ---- S = Q K^T (bf16x2 split, 3 passes) ----
            float sS[16][4];
#pragma unroll
            for (int f = 0; f < 16; f++)
#pragma unroll
                for (int e = 0; e < 4; e++) sS[f][e] = 0.f;

#pragma unroll
            for (int s = 0; s < 4; s++) {
                uint32_t ah0, ah1, ah2, ah3, al0, al1, al2, al3;
                ldsm4(ah0, ah1, ah2, ah3, QHI + a_lane + s * 32);
                ldsm4(al0, al1, al2, al3, QLO + a_lane + s * 32);
#pragma unroll
                for (int p = 0; p < 8; p++) {
                    uint32_t bh0, bh1, bh2, bh3, bl0, bl1, bl2, bl3;
                    ldsm4(bh0, bh1, bh2, bh3, KHI + kb_lane + p * 2304 + s * 32);
                    ldsm4(bl0, bl1, bl2, bl3, KLO + kb_lane + p * 2304 + s * 32);
                    mma_bf16(sS[2*p],   ah0, ah1, ah2, ah3, bh0, bh2);
                    mma_bf16(sS[2*p+1], ah0, ah1, ah2, ah3, bh1, bh3);
                    mma_bf16(sS[2*p],   ah0, ah1, ah2, ah3, bl0, bl2);
                    mma_bf16(sS[2*p+1], ah0, ah1, ah2, ah3, bl1, bl3);
                    mma_bf16(sS[2*p],   al0, al1, al2, al3, bh0, bh2);
                    mma_bf16(sS[2*p+1], al0, al1, al2, al3, bh1, bh3);
                }
            }

            // ---- mask only boundary tiles ----
            const bool needmask = !((c0 >= Q0w + 15) && (c0 + 127 <= Q0w + 1024));
            if (needmask) {
#pragma unroll
                for (int f = 0; f < 16; f++) {
                    int c = c0 + f * 8 + (lane & 3) * 2;
#pragma unroll
                    for (int e = 0; e < 2; e++) {
                        int cc = c + e;
                        if (!(cc >= r0 && cc <= r0 + 1024)) sS[f][e]     = -1e30f;
                        if (!(cc >= r1 && cc <= r1 + 1024)) sS[f][2 + e] = -1e30f;
                    }
                }
            }

            // ---- row max + rescale (log2 domain) ----
            float tm0 = -1e30f, tm1 = -1e30f;
#pragma unroll
            for (int f = 0; f < 16; f++) {
                tm0 = fmaxf(tm0, fmaxf(sS[f][0], sS[f][1]));
                tm1 = fmaxf(tm1, fmaxf(sS[f][2], sS[f][3]));
            }
            tm0 = fmaxf(tm0, __shfl_xor_sync(0xffffffffu, tm0, 1));
            tm0 = fmaxf(tm0, __shfl_xor_sync(0xffffffffu, tm0, 2));
            tm1 = fmaxf(tm1, __shfl_xor_sync(0xffffffffu, tm1, 1));
            tm1 = fmaxf(tm1, __shfl_xor_sync(0xffffffffu, tm1, 2));
            float nm0 = fmaxf(m0r, tm0), nm1 = fmaxf(m1r, tm1);
            float cr0 = ex2(m0r - nm0), cr1 = ex2(m1r - nm1);
            m0r = nm0; m1r = nm1;
#pragma unroll
            for (int f = 0; f < 8; f++) {
                o[f][0] *= cr0; o[f][1] *= cr0;
                o[f][2] *= cr1; o[f][3] *= cr1;
            }
            float la0 = 0.f, la1 = 0.f;

            // ---- P V (exp2 fused, fp16 2-pass: Ph*Vh + Ph*Vl) ----
#pragma unroll
            for (int s2 = 0; s2 < 8; s2++) {
                int f0 = 2 * s2, f1 = f0 + 1;
                float p00 = ex2(sS[f0][0] - m0r), p01 = ex2(sS[f0][1] - m0r);
                float p02 = ex2(sS[f0][2] - m1r), p03 = ex2(sS[f0][3] - m1r);
                float p10 = ex2(sS[f1][0] - m0r), p11 = ex2(sS[f1][1] - m0r);
                float p12 = ex2(sS[f1][2] - m1r), p13 = ex2(sS[f1][3] - m1r);
                la0 += p00 + p01 + p10 + p11;
                la1 += p02 + p03 + p12 + p13;
                uint32_t ah0 = pack_h2(p00, p01);
                uint32_t ah1 = pack_h2(p02, p03);
                uint32_t ah2 = pack_h2(p10, p11);
                uint32_t ah3 = pack_h2(p12, p13);
#pragma unroll
                for (int q = 0; q < 4; q++) {
                    uint32_t bh0, bh1, bh2, bh3, bl0, bl1, bl2, bl3;
                    ldsm4t(bh0, bh1, bh2, bh3, VHI + vb_lane + s2 * 2304 + q * 32);
                    ldsm4t(bl0, bl1, bl2, bl3, VLO + vb_lane + s2 * 2304 + q * 32);
                    mma_f16(o[2*q],   ah0, ah1, ah2, ah3, bh0, bh2);
                    mma_f16(o[2*q+1], ah0, ah1, ah2, ah3, bh1, bh3);
                    mma_f16(o[2*q],   ah0, ah1, ah2, ah3, bl0, bl2);
                    mma_f16(o[2*q+1], ah0, ah1, ah2, ah3, bl1, bl3);
                }
            }
            la0 += __shfl_xor_sync(0xffffffffu, la0, 1);
            la0 += __shfl_xor_sync(0xffffffffu, la0, 2);
            la1 += __shfl_xor_sync(0xffffffffu, la1, 1);
            la1 += __shfl_xor_sync(0xffffffffu, la1, 2);
            l0r = l0r * cr0 + la0;
            l1r = l1r * cr1 + la1;
        }

        __syncthreads();
        if (i + 2 < nt) {
            fetch(tiles[i + 2], i & 1);
            asm volatile("cp.async.commit_group;" ::: "memory");
        }
    }

    // ---- normalize + store (tf32-rounded for the output GEMM) ----
    const float i0 = 1.f / l0r, i1 = 1.f / l1r;
    const int sg0 = w * WSZ + q0 + warp * 16 + (lane >> 2);
    float* dst0 = g_att + (size_t)sg0 * E_DIM + h * HD + (lane & 3) * 2;
    float* dst1 = dst0 + 8 * E_DIM;
#pragma unroll
    for (int f = 0; f < 8; f++) {
        *(float2*)(dst0 + f * 8) = make_float2(rtf(o[f][0] * i0), rtf(o[f][1] * i0));
        *(float2*)(dst1 + f * 8) = make_float2(rtf(o[f][2] * i1), rtf(o[f][3] * i1));
    }
}

// ---------------------------------------------------------------------------
extern "C" void kernel_launch(void* const* d_in, const int* in_sizes, int n_in,
                              void* d_out, int out_size)
{
    const float* x  = (const float*)d_in[0];
    const float* wq = (const float*)d_in[1];
    const float* bq = (const float*)d_in[2];
    const float* wk = (const float*)d_in[3];
    const float* bk = (const float*)d_in[4];
    const float* wv = (const float*)d_in[5];
    const float* bv = (const float*)d_in[6];
    const float* wo = (const float*)d_in[7];
    const float* bo = (const float*)d_in[8];
    float* out = (float*)d_out;

    __nv_bfloat16 *qh, *ql, *kh, *kl;
    __half *vh, *vl;
    float *att, *rnd;
    cudaGetSymbolAddress((void**)&qh, g_qh);
    cudaGetSymbolAddress((void**)&ql, g_ql);
    cudaGetSymbolAddress((void**)&kh, g_kh);
    cudaGetSymbolAddress((void**)&kl, g_kl);
    cudaGetSymbolAddress((void**)&vh, g_vh);
    cudaGetSymbolAddress((void**)&vl, g_vl);
    cudaGetSymbolAddress((void**)&att, g_att);
    cudaGetSymbolAddress((void**)&rnd, g_rnd);

    const float* xr  = rnd;
    const float* wqr = rnd + 4 * 1024 * 1024;
    const float* wkr = rnd + 5 * 1024 * 1024;
    const float* wvr = rnd + 6 * 1024 * 1024;
    const float* wor = rnd + 7 * 1024 * 1024;

    const int gsm = 2 * GSTG;          // 73728
    cudaFuncSetAttribute(gemm_tf32_kernel<0>, cudaFuncAttributeMaxDynamicSharedMemorySize, gsm);
    cudaFuncSetAttribute(gemm_tf32_kernel<1>, cudaFuncAttributeMaxDynamicSharedMemorySize, gsm);
    cudaFuncSetAttribute(gemm_tf32_kernel<2>, cudaFuncAttributeMaxDynamicSharedMemorySize, gsm);
    cudaFuncSetAttribute(gemm_tf32_kernel<3>, cudaFuncAttributeMaxDynamicSharedMemorySize, gsm);
    const int asm_b = 10 * REG;        // 184320
    cudaFuncSetAttribute(attn_kernel, cudaFuncAttributeMaxDynamicSharedMemorySize, asm_b);

    preround_kernel<<<8192, 256>>>((const float4*)x, (const float4*)wq, (const float4*)wk,
                                   (const float4*)wv, (const float4*)wo, (float4*)rnd);

    dim3 gg(E_DIM / 128, S_LEN / 128);
    gemm_tf32_kernel<2><<<gg, 256, gsm>>>(xr, wqr, bq, nullptr, qh, ql, nullptr, nullptr);
    gemm_tf32_kernel<1><<<gg, 256, gsm>>>(xr, wkr, bk, nullptr, kh, kl, nullptr, nullptr);
    gemm_tf32_kernel<3><<<gg, 256, gsm>>>(xr, wvr, bv, nullptr, nullptr, nullptr, vh, vl);

    dim3 ga(4, 8, 16);
    attn_kernel<<<ga, 256, asm_b>>>();

    gemm_tf32_kernel<0><<<gg, 256, gsm>>>(att, wor, bo, out, nullptr, nullptr, nullptr, nullptr);
}

// round 9
// speedup vs baseline: 4.4255x; 1.0243x over previous
#include <cuda_runtime.h>
#include <cuda_bf16.h>
#include <cuda_fp16.h>
#include <cstdint>

#define S_LEN 4096
#define E_DIM 1024
#define H_NUM 16
#define HD    64
#define WSZ   512
#define NTILE 12
#define LOG2E 1.4426950408889634f

// Scratch (allocation-free rule: __device__ globals).
#define PLANE (H_NUM * S_LEN * HD)
__device__ __nv_bfloat16 g_qh[PLANE], g_ql[PLANE];   // Q * log2(e), bf16 split
__device__ __nv_bfloat16 g_kh[PLANE], g_kl[PLANE];   // K bf16 split
__device__ __half        g_vh[PLANE], g_vl[PLANE];   // V fp16 split
__device__ float g_att[S_LEN * E_DIM];               // tf32-rounded attention out
__device__ float g_rnd[8 * 1024 * 1024];             // tf32-rounded x | wq wk wv wo

// ---------------------------------------------------------------------------
// helpers
// ---------------------------------------------------------------------------
__device__ __forceinline__ uint32_t f2tf32(float x) {
    uint32_t r;
    asm("cvt.rna.tf32.f32 %0, %1;" : "=r"(r) : "f"(x));
    return r;
}
__device__ __forceinline__ float rtf(float x) { return __uint_as_float(f2tf32(x)); }
__device__ __forceinline__ float ex2(float x) {
    float r;
    asm("ex2.approx.f32 %0, %1;" : "=f"(r) : "f"(x));
    return r;
}
__device__ __forceinline__ void ldsm4(uint32_t& r0, uint32_t& r1, uint32_t& r2,
                                      uint32_t& r3, uint32_t addr) {
    asm volatile("ldmatrix.sync.aligned.m8n8.x4.shared.b16 {%0,%1,%2,%3}, [%4];"
                 : "=r"(r0), "=r"(r1), "=r"(r2), "=r"(r3) : "r"(addr));
}
__device__ __forceinline__ void ldsm4t(uint32_t& r0, uint32_t& r1, uint32_t& r2,
                                       uint32_t& r3, uint32_t addr) {
    asm volatile("ldmatrix.sync.aligned.m8n8.x4.trans.shared.b16 {%0,%1,%2,%3}, [%4];"
                 : "=r"(r0), "=r"(r1), "=r"(r2), "=r"(r3) : "r"(addr));
}
__device__ __forceinline__ void mma_tf32(float c[4], const uint32_t a[4],
                                         uint32_t b0, uint32_t b1) {
    asm volatile(
        "mma.sync.aligned.m16n8k8.row.col.f32.tf32.tf32.f32 "
        "{%0,%1,%2,%3},{%4,%5,%6,%7},{%8,%9},{%0,%1,%2,%3};"
        : "+f"(c[0]), "+f"(c[1]), "+f"(c[2]), "+f"(c[3])
        : "r"(a[0]), "r"(a[1]), "r"(a[2]), "r"(a[3]), "r"(b0), "r"(b1));
}
__device__ __forceinline__ void mma_bf16(float c[4],
                                         uint32_t a0, uint32_t a1, uint32_t a2, uint32_t a3,
                                         uint32_t b0, uint32_t b1) {
    asm volatile(
        "mma.sync.aligned.m16n8k16.row.col.f32.bf16.bf16.f32 "
        "{%0,%1,%2,%3},{%4,%5,%6,%7},{%8,%9},{%0,%1,%2,%3};"
        : "+f"(c[0]), "+f"(c[1]), "+f"(c[2]), "+f"(c[3])
        : "r"(a0), "r"(a1), "r"(a2), "r"(a3), "r"(b0), "r"(b1));
}
__device__ __forceinline__ void mma_f16(float c[4],
                                        uint32_t a0, uint32_t a1, uint32_t a2, uint32_t a3,
                                        uint32_t b0, uint32_t b1) {
    asm volatile(
        "mma.sync.aligned.m16n8k16.row.col.f32.f16.f16.f32 "
        "{%0,%1,%2,%3},{%4,%5,%6,%7},{%8,%9},{%0,%1,%2,%3};"
        : "+f"(c[0]), "+f"(c[1]), "+f"(c[2]), "+f"(c[3])
        : "r"(a0), "r"(a1), "r"(a2), "r"(a3), "r"(b0), "r"(b1));
}
__device__ __forceinline__ uint32_t pack_bf2(float x0, float x1) {
    uint32_t r;
    asm("cvt.rn.bf16x2.f32 %0, %1, %2;" : "=r"(r) : "f"(x1), "f"(x0));
    return r;
}
__device__ __forceinline__ uint32_t pack_h2(float x0, float x1) {
    uint32_t r;
    asm("cvt.rn.f16x2.f32 %0, %1, %2;" : "=r"(r) : "f"(x1), "f"(x0));
    return r;
}
__device__ __forceinline__ void split2(float x0, float x1, uint32_t& h, uint32_t& l) {
    h = pack_bf2(x0, x1);
    float f0 = __uint_as_float(h << 16);
    float f1 = __uint_as_float(h & 0xffff0000u);
    l = pack_bf2(x0 - f0, x1 - f1);
}
__device__ __forceinline__ void split2h(float x0, float x1, uint32_t& h, uint32_t& l) {
    h = pack_h2(x0, x1);
    __half2 hv = *reinterpret_cast<__half2*>(&h);
    l = pack_h2(x0 - __half2float(hv.x), x1 - __half2float(hv.y));
}
__device__ __forceinline__ void cp16(uint32_t s, const void* g) {
    asm volatile("cp.async.cg.shared.global [%0], [%1], 16;" :: "r"(s), "l"(g));
}

// ---------------------------------------------------------------------------
// Pre-round x and the 4 weights to the tf32 grid (idempotent, into scratch).
// ---------------------------------------------------------------------------
__global__ __launch_bounds__(256)
void preround_kernel(const float4* __restrict__ x,  const float4* __restrict__ wq,
                     const float4* __restrict__ wk, const float4* __restrict__ wv,
                     const float4* __restrict__ wo, float4* __restrict__ out)
{
    int i = blockIdx.x * 256 + threadIdx.x;
    const float4* src;
    int j;
    if (i < (1 << 20)) { src = x; j = i; }
    else {
        int t = i - (1 << 20);
        int wsel = t >> 18;
        j = t & ((1 << 18) - 1);
        src = (wsel == 0) ? wq : (wsel == 1) ? wk : (wsel == 2) ? wv : wo;
    }
    float4 v = src[j];
    out[i] = make_float4(rtf(v.x), rtf(v.y), rtf(v.z), rtf(v.w));
}

// ---------------------------------------------------------------------------
// tf32 GEMM core: 4-stage cp.async pipeline, ONE sync per iteration.
// CTA 128x128, BK=16, 8 warps (2m x 4n), warp tile 64x32.
// Row stride 20 floats (80B) -> conflict-free ldmatrix.
// ---------------------------------------------------------------------------
#define GST  20480   // bytes per stage (A 10240 + B 10240)
#define NKS  (E_DIM / 16)

struct GemmAcc { float a[4][4][4]; };

__device__ __forceinline__ void gemm_core(const float* __restrict__ A,
                                          const float* __restrict__ W,
                                          int m0, int n0, char* smc, GemmAcc& G)
{
    const uint32_t smu = (uint32_t)__cvta_generic_to_shared(smc);
    const int tid  = threadIdx.x;
    const int warp = tid >> 5, lane = tid & 31;
    const int wm = warp >> 2, wn = warp & 3;

#pragma unroll
    for (int i = 0; i < 4; i++)
#pragma unroll
        for (int j = 0; j < 4; j++)
#pragma unroll
            for (int r = 0; r < 4; r++) G.a[i][j][r] = 0.f;

    const int a_row = (lane & 7) + ((lane >> 3) & 1) * 8;
    const int a_k   = (lane >> 4) * 4;
    const int b_row = (lane & 7) + (lane >> 4) * 8;
    const int b_k   = ((lane >> 3) & 1) * 4;
    const uint32_t aoff = (wm * 64 + a_row) * 80 + a_k * 4;
    const uint32_t boff = 10240u + (wn * 32 + b_row) * 80 + b_k * 4;

    auto fetchg = [&](int ks, int st) {
        int k0 = ks * 16;
        uint32_t sb = smu + (uint32_t)st * GST;
#pragma unroll
        for (int u = 0; u < 2; u++) {
            int f = tid + u * 256;                 // 512 float4 per operand
            int row = f >> 2, c = f & 3;
            cp16(sb + row * 80 + c * 16,
                 A + (size_t)(m0 + row) * E_DIM + k0 + c * 4);
            cp16(sb + 10240 + row * 80 + c * 16,
                 W + (size_t)(n0 + row) * E_DIM + k0 + c * 4);
        }
    };
    fetchg(0, 0);
    asm volatile("cp.async.commit_group;" ::: "memory");
    fetchg(1, 1);
    asm volatile("cp.async.commit_group;" ::: "memory");
    fetchg(2, 2);
    asm volatile("cp.async.commit_group;" ::: "memory");

    for (int ks = 0; ks < NKS; ks++) {
        asm volatile("cp.async.wait_group 2;" ::: "memory");
        __syncthreads();

        const uint32_t sb = smu + (uint32_t)(ks & 3) * GST;
#pragma unroll
        for (int kk = 0; kk < 2; kk++) {
            uint32_t a[4][4], b[2][4];
#pragma unroll
            for (int i = 0; i < 4; i++)
                ldsm4(a[i][0], a[i][1], a[i][2], a[i][3],
                      sb + aoff + (uint32_t)(i * 16 * 80 + kk * 32));
#pragma unroll
            for (int p = 0; p < 2; p++)
                ldsm4(b[p][0], b[p][1], b[p][2], b[p][3],
                      sb + boff + (uint32_t)(p * 16 * 80 + kk * 32));
#pragma unroll
            for (int i = 0; i < 4; i++)
#pragma unroll
                for (int j = 0; j < 4; j++) {
                    int p = j >> 1, off = (j & 1) * 2;
                    mma_tf32(G.a[i][j], a[i], b[p][off], b[p][off + 1]);
                }
        }
        // fetch into the stage consumed at ks-1 (freed by the sync above)
        if (ks + 3 < NKS) fetchg(ks + 3, (ks + 3) & 3);
        asm volatile("cp.async.commit_group;" ::: "memory");   // may be empty
    }
}

// Fused QKV projections: gridDim.z selects Q/K/V (weights, bias, epilogue).
__global__ __launch_bounds__(256, 2)
void gemm_qkv_kernel(const float* __restrict__ xr, const float* __restrict__ wbase,
                     const float* __restrict__ bq, const float* __restrict__ bk,
                     const float* __restrict__ bv)
{
    extern __shared__ char smc[];
    const int z = blockIdx.z;
    const float* W = wbase + (size_t)z * (1 << 20);      // wq | wk | wv (rounded)
    const float* bias = (z == 0) ? bq : (z == 1) ? bk : bv;
    const int m0 = blockIdx.y * 128, n0 = blockIdx.x * 128;

    GemmAcc G;
    gemm_core(xr, W, m0, n0, smc, G);

    const int warp = threadIdx.x >> 5, lane = threadIdx.x & 31;
    const int wm = warp >> 2, wn = warp & 3;
#pragma unroll
    for (int i = 0; i < 4; i++) {
#pragma unroll
        for (int j = 0; j < 4; j++) {
            int row = m0 + wm * 64 + i * 16 + (lane >> 2);
            int col = n0 + wn * 32 + j * 8 + (lane & 3) * 2;
#pragma unroll
            for (int rp = 0; rp < 2; rp++) {
                int rr = row + rp * 8;
                float v0 = G.a[i][j][rp * 2 + 0] + bias[col];
                float v1 = G.a[i][j][rp * 2 + 1] + bias[col + 1];
                int hh = col >> 6, d = col & 63;
                size_t off = ((size_t)hh * S_LEN + rr) * HD + d;
                if (z == 2) {
                    uint32_t hp, lp;
                    split2h(v0, v1, hp, lp);
                    *(uint32_t*)(g_vh + off) = hp;
                    *(uint32_t*)(g_vl + off) = lp;
                } else {
                    if (z == 0) { v0 *= LOG2E; v1 *= LOG2E; }
                    uint32_t hp, lp;
                    split2(v0, v1, hp, lp);
                    if (z == 0) {
                        *(uint32_t*)(g_qh + off) = hp;
                        *(uint32_t*)(g_ql + off) = lp;
                    } else {
                        *(uint32_t*)(g_kh + off) = hp;
                        *(uint32_t*)(g_kl + off) = lp;
                    }
                }
            }
        }
    }
}

// Output GEMM: out = att @ wo^T + bo, f32 [s][e].
__global__ __launch_bounds__(256, 2)
void gemm_out_kernel(const float* __restrict__ A, const float* __restrict__ W,
                     const float* __restrict__ bias, float* __restrict__ dst)
{
    extern __shared__ char smc[];
    const int m0 = blockIdx.y * 128, n0 = blockIdx.x * 128;
    GemmAcc G;
    gemm_core(A, W, m0, n0, smc, G);

    const int warp = threadIdx.x >> 5, lane = threadIdx.x & 31;
    const int wm = warp >> 2, wn = warp & 3;
#pragma unroll
    for (int i = 0; i < 4; i++) {
#pragma unroll
        for (int j = 0; j < 4; j++) {
            int row = m0 + wm * 64 + i * 16 + (lane >> 2);
            int col = n0 + wn * 32 + j * 8 + (lane & 3) * 2;
#pragma unroll
            for (int rp = 0; rp < 2; rp++) {
                int rr = row + rp * 8;
                float v0 = G.a[i][j][rp * 2 + 0] + bias[col];
                float v1 = G.a[i][j][rp * 2 + 1] + bias[col + 1];
                *(float2*)(dst + (size_t)rr * E_DIM + col) = make_float2(v0, v1);
            }
        }
    }
}

// ---------------------------------------------------------------------------
// Windowed attention (unchanged from R8): QK bf16x2-split 3-pass, PV fp16
// 2-pass, log2-domain softmax, cp.async double buffer, closed-form pads.
// ---------------------------------------------------------------------------
#define RS   72
#define REG  (128 * RS * 2)
__global__ __launch_bounds__(256)
void attn_kernel()
{
    extern __shared__ char smc[];
    const uint32_t smu = (uint32_t)__cvta_generic_to_shared(smc);
    const uint32_t QHI = smu, QLO = smu + REG;

    const int tid  = threadIdx.x;
    const int warp = tid >> 5, lane = tid & 31;
    const int q0   = blockIdx.x * 128;
    const int w    = blockIdx.y;
    const int h    = blockIdx.z;
    const int base = w * WSZ - WSZ;
    const int Q0w  = q0 + warp * 16;

    const uint32_t a_lane = (uint32_t)(((warp * 16 + (lane & 7) + ((lane >> 3) & 1) * 8) * RS
                                        + (lane >> 4) * 8) * 2);
    const uint32_t kb_lane = (uint32_t)((((lane & 7) + ((lane >> 3) & 1) * 8) * RS
                                        + (lane >> 4) * 8) * 2);
    const uint32_t vb_lane = (uint32_t)((((lane & 7) + ((lane >> 4) & 1) * 8) * RS
                                        + ((lane >> 3) & 1) * 8) * 2);

    int tiles[12], nt = 0, npad = 0;
#pragma unroll
    for (int kt = 0; kt < NTILE; kt++) {
        int c0 = kt * 128, t0 = base + c0;
        if (t0 < 0 || t0 >= S_LEN) { npad++; continue; }
        if ((c0 + 127 >= q0) && (c0 <= q0 + 127 + 1024)) tiles[nt++] = kt;
    }

    {
        size_t qoff = ((size_t)h * S_LEN + w * WSZ + q0) * HD;
        for (int f = tid; f < 1024; f += 256) {
            int r = f >> 3, c = f & 7;
            uint32_t so = r * 144 + c * 16;
            size_t go = qoff + (size_t)r * HD + c * 8;
            cp16(QHI + so, g_qh + go);
            cp16(QLO + so, g_ql + go);
        }
    }
    const size_t hoff = (size_t)h * S_LEN * HD;
    auto fetch = [&](int kt, int b) {
        int t0 = base + kt * 128;
        uint32_t sb = smu + (uint32_t)(2 + 4 * b) * REG;
        size_t gb = hoff + (size_t)t0 * HD;
        for (int f = tid; f < 1024; f += 256) {
            int r = f >> 3, c = f & 7;
            uint32_t so = sb + r * 144 + c * 16;
            size_t go = gb + (size_t)r * HD + c * 8;
            cp16(so,           g_kh + go);
            cp16(so + REG,     g_kl + go);
            cp16(so + 2 * REG, g_vh + go);
            cp16(so + 3 * REG, g_vl + go);
        }
    };
    fetch(tiles[0], 0);
    asm volatile("cp.async.commit_group;" ::: "memory");
    if (nt > 1) {
        fetch(tiles[1], 1);
        asm volatile("cp.async.commit_group;" ::: "memory");
    }

    float m0r = -1e30f, m1r = -1e30f, l0r = 0.f, l1r = 0.f;
    float o[8][4];
#pragma unroll
    for (int f = 0; f < 8; f++)
#pragma unroll
        for (int e = 0; e < 4; e++) o[f][e] = 0.f;

    const int r0 = Q0w + (lane >> 2);
    const int r1 = r0 + 8;

    for (int i = 0; i < nt; i++) {
        if (i + 1 < nt) asm volatile("cp.async.wait_group 1;" ::: "memory");
        else            asm volatile("cp.async.wait_group 0;" ::: "memory");
        __syncthreads();

        if (i == 0) {
            const __nv_bfloat16* qh = (const __nv_bfloat16*)smc;
            const __nv_bfloat16* ql = (const __nv_bfloat16*)(smc + REG);
            int lr0 = warp * 16 + (lane >> 2);
            float qs0 = 0.f, qs1 = 0.f;
#pragma unroll
            for (int d = 0; d < HD; d++) {
                qs0 += __bfloat162float(qh[lr0 * RS + d]) + __bfloat162float(ql[lr0 * RS + d]);
                qs1 += __bfloat162float(qh[(lr0 + 8) * RS + d]) + __bfloat162float(ql[(lr0 + 8) * RS + d]);
            }
            if (npad) {
                float s0 = -qs0, s1 = -qs1;
                float nm0 = fmaxf(m0r, s0), nm1 = fmaxf(m1r, s1);
                float cr0 = ex2(m0r - nm0), cr1 = ex2(m1r - nm1);
                m0r = nm0; m1r = nm1;
                float p0 = ex2(s0 - nm0) * (128.f * npad);
                float p1 = ex2(s1 - nm1) * (128.f * npad);
                l0r = l0r * cr0 + p0;
                l1r = l1r * cr1 + p1;
#pragma unroll
                for (int f = 0; f < 8; f++) {
                    o[f][0] = o[f][0] * cr0 - p0;
                    o[f][1] = o[f][1] * cr0 - p0;
                    o[f][2] = o[f][2] * cr1 - p1;
                    o[f][3] = o[f][3] * cr1 - p1;
                }
            }
        }

        const int kt = tiles[i];
        const int c0 = kt * 128;
        const bool relevant = (c0 + 127 >= Q0w) && (c0 <= Q0w + 1039);

        if (relevant) {
            const uint32_t BB  = smu + (uint32_t)(2 + 4 * (i & 1)) * REG;
            const uint32_t KHI = BB, KLO = BB + REG, VHI = BB + 2 * REG, VLO = BB + 3 * REG;

            float sS[16][4];
#pragma unroll
            for (int f = 0; f < 16; f++)
#pragma unroll
                for (int e = 0; e < 4; e++) sS[f][e] = 0.f;

#pragma unroll
            for (int s = 0; s < 4; s++) {
                uint32_t ah0, ah1, ah2, ah3, al0, al1, al2, al3;
                ldsm4(ah0, ah1, ah2, ah3, QHI + a_lane + s * 32);
                ldsm4(al0, al1, al2, al3, QLO + a_lane + s * 32);
#pragma unroll
                for (int p = 0; p < 8; p++) {
                    uint32_t bh0, bh1, bh2, bh3, bl0, bl1, bl2, bl3;
                    ldsm4(bh0, bh1, bh2, bh3, KHI + kb_lane + p * 2304 + s * 32);
                    ldsm4(bl0, bl1, bl2, bl3, KLO + kb_lane + p * 2304 + s * 32);
                    mma_bf16(sS[2*p],   ah0, ah1, ah2, ah3, bh0, bh2);
                    mma_bf16(sS[2*p+1], ah0, ah1, ah2, ah3, bh1, bh3);
                    mma_bf16(sS[2*p],   ah0, ah1, ah2, ah3, bl0, bl2);
                    mma_bf16(sS[2*p+1], ah0, ah1, ah2, ah3, bl1, bl3);
                    mma_bf16(sS[2*p],   al0, al1, al2, al3, bh0, bh2);
                    mma_bf16(sS[2*p+1], al0, al1, al2, al3, bh1, bh3);
                }
            }

            const bool needmask = !((c0 >= Q0w + 15) && (c0 + 127 <= Q0w + 1024));
            if (needmask) {
#pragma unroll
                for (int f = 0; f < 16; f++) {
                    int c = c0 + f * 8 + (lane & 3) * 2;
#pragma unroll
                    for (int e = 0; e < 2; e++) {
                        int cc = c + e;
                        if (!(cc >= r0 && cc <= r0 + 1024)) sS[f][e]     = -1e30f;
                        if (!(cc >= r1 && cc <= r1 + 1024)) sS[f][2 + e] = -1e30f;
                    }
                }
            }

            float tm0 = -1e30f, tm1 = -1e30f;
#pragma unroll
            for (int f = 0; f < 16; f++) {
                tm0 = fmaxf(tm0, fmaxf(sS[f][0], sS[f][1]));
                tm1 = fmaxf(tm1, fmaxf(sS[f][2], sS[f][3]));
            }
            tm0 = fmaxf(tm0, __shfl_xor_sync(0xffffffffu, tm0, 1));
            tm0 = fmaxf(tm0, __shfl_xor_sync(0xffffffffu, tm0, 2));
            tm1 = fmaxf(tm1, __shfl_xor_sync(0xffffffffu, tm1, 1));
            tm1 = fmaxf(tm1, __shfl_xor_sync(0xffffffffu, tm1, 2));
            float nm0 = fmaxf(m0r, tm0), nm1 = fmaxf(m1r, tm1);
            float cr0 = ex2(m0r - nm0), cr1 = ex2(m1r - nm1);
            m0r = nm0; m1r = nm1;
#pragma unroll
            for (int f = 0; f < 8; f++) {
                o[f][0] *= cr0; o[f][1] *= cr0;
                o[f][2] *= cr1; o[f][3] *= cr1;
            }
            float la0 = 0.f, la1 = 0.f;

#pragma unroll
            for (int s2 = 0; s2 < 8; s2++) {
                int f0 = 2 * s2, f1 = f0 + 1;
                float p00 = ex2(sS[f0][0] - m0r), p01 = ex2(sS[f0][1] - m0r);
                float p02 = ex2(sS[f0][2] - m1r), p03 = ex2(sS[f0][3] - m1r);
                float p10 = ex2(sS[f1][0] - m0r), p11 = ex2(sS[f1][1] - m0r);
                float p12 = ex2(sS[f1][2] - m1r), p13 = ex2(sS[f1][3] - m1r);
                la0 += p00 + p01 + p10 + p11;
                la1 += p02 + p03 + p12 + p13;
                uint32_t ah0 = pack_h2(p00, p01);
                uint32_t ah1 = pack_h2(p02, p03);
                uint32_t ah2 = pack_h2(p10, p11);
                uint32_t ah3 = pack_h2(p12, p13);
#pragma unroll
                for (int q = 0; q < 4; q++) {
                    uint32_t bh0, bh1, bh2, bh3, bl0, bl1, bl2, bl3;
                    ldsm4t(bh0, bh1, bh2, bh3, VHI + vb_lane + s2 * 2304 + q * 32);
                    ldsm4t(bl0, bl1, bl2, bl3, VLO + vb_lane + s2 * 2304 + q * 32);
                    mma_f16(o[2*q],   ah0, ah1, ah2, ah3, bh0, bh2);
                    mma_f16(o[2*q+1], ah0, ah1, ah2, ah3, bh1, bh3);
                    mma_f16(o[2*q],   ah0, ah1, ah2, ah3, bl0, bl2);
                    mma_f16(o[2*q+1], ah0, ah1, ah2, ah3, bl1, bl3);
                }
            }
            la0 += __shfl_xor_sync(0xffffffffu, la0, 1);
            la0 += __shfl_xor_sync(0xffffffffu, la0, 2);
            la1 += __shfl_xor_sync(0xffffffffu, la1, 1);
            la1 += __shfl_xor_sync(0xffffffffu, la1, 2);
            l0r = l0r * cr0 + la0;
            l1r = l1r * cr1 + la1;
        }

        __syncthreads();
        if (i + 2 < nt) {
            fetch(tiles[i + 2], i & 1);
            asm volatile("cp.async.commit_group;" ::: "memory");
        }
    }

    const float i0 = 1.f / l0r, i1 = 1.f / l1r;
    const int sg0 = w * WSZ + q0 + warp * 16 + (lane >> 2);
    float* dst0 = g_att + (size_t)sg0 * E_DIM + h * HD + (lane & 3) * 2;
    float* dst1 = dst0 + 8 * E_DIM;
#pragma unroll
    for (int f = 0; f < 8; f++) {
        *(float2*)(dst0 + f * 8) = make_float2(rtf(o[f][0] * i0), rtf(o[f][1] * i0));
        *(float2*)(dst1 + f * 8) = make_float2(rtf(o[f][2] * i1), rtf(o[f][3] * i1));
    }
}

// ---------------------------------------------------------------------------
extern "C" void kernel_launch(void* const* d_in, const int* in_sizes, int n_in,
                              void* d_out, int out_size)
{
    const float* x  = (const float*)d_in[0];
    const float* wq = (const float*)d_in[1];
    const float* bq = (const float*)d_in[2];
    const float* wk = (const float*)d_in[3];
    const float* bk = (const float*)d_in[4];
    const float* wv = (const float*)d_in[5];
    const float* bv = (const float*)d_in[6];
    const float* wo = (const float*)d_in[7];
    const float* bo = (const float*)d_in[8];
    float* out = (float*)d_out;

    float *att, *rnd;
    cudaGetSymbolAddress((void**)&att, g_att);
    cudaGetSymbolAddress((void**)&rnd, g_rnd);

    const float* xr  = rnd;
    const float* wqr = rnd + 4 * 1024 * 1024;      // wq wk wv contiguous
    const float* wor = rnd + 7 * 1024 * 1024;

    const int gsm = 4 * GST;          // 81920
    cudaFuncSetAttribute(gemm_qkv_kernel, cudaFuncAttributeMaxDynamicSharedMemorySize, gsm);
    cudaFuncSetAttribute(gemm_out_kernel, cudaFuncAttributeMaxDynamicSharedMemorySize, gsm);
    const int asm_b = 10 * REG;       // 184320
    cudaFuncSetAttribute(attn_kernel, cudaFuncAttributeMaxDynamicSharedMemorySize, asm_b);

    preround_kernel<<<8192, 256>>>((const float4*)x, (const float4*)wq, (const float4*)wk,
                                   (const float4*)wv, (const float4*)wo, (float4*)rnd);

    dim3 gq(E_DIM / 128, S_LEN / 128, 3);
    gemm_qkv_kernel<<<gq, 256, gsm>>>(xr, wqr, bq, bk, bv);

    dim3 ga(4, 8, 16);
    attn_kernel<<<ga, 256, asm_b>>>();

    dim3 gg(E_DIM / 128, S_LEN / 128);
    gemm_out_kernel<<<gg, 256, gsm>>>(att, wor, bo, out);
}